// round 14
// baseline (speedup 1.0000x reference)
#include <cuda_runtime.h>
#include <cuda_fp16.h>
#include <cstdint>
#include <cstddef>

// ---------------------------------------------------------------------------
// MultiHeadMemory: H=16, M=1024, D=512, O=512, N=16384
// fp16 mma.sync engine at the legacy-HMMA roofline (~288 TF/s).
// R14: (a) mode-2 exp reverted to fp32 __expf (restores rel_err margin);
// (b) GEMM4 split into 4 head-group launches; GEMM6 split g consumes its
// group's atth slice on sB while GEMM4(g+1) runs -> L2-resident handoff.
//
// spine (s0): cvt mems, cvt Wk -> GEMM1(exp) -> [eK] GEMM4 g0..g3 (ev4[g])
//             -> [eG6] reduce(+bias)
// sB:  [fork] cvt Wv -> [eMems] GEMM2 -> [eWf] GEMM3b -> GEMM6 g0..g3 -> eG6
// sC:  [fork] cvt k -> eK ; cvt Wf -> eWf
// ---------------------------------------------------------------------------

#define H_  16
#define M_  1024
#define D_  512
#define O_  512
#define N_  16384

#define TBM 128
#define TBN 128
#define TBK 32          // halves per k-tile
#define ROWB 80         // bytes per SMEM row: 64 B data + 16 B pad
#define NSTG 3
#define STGB (2 * TBM * ROWB)            // A+B per stage = 20480 B
#define SCALEBUF 2048                    // smem bytes for fused scale buffers
#define SMEM_DYN (NSTG * STGB + SCALEBUF)    // 63488 B

#define MTILES   8                        // GEMM4 col tiles (M_/TBN)
#define ROWS_TOT (H_ * N_)                // 262144 softmax5 rows
#define MT3      4                        // GEMM1 col tiles (O_/TBN)
#define ROWS3    (H_ * M_)                // 16384 softmax3 rows
#define NGRP     4                        // head groups (producer/consumer)
#define HPS      (H_ / NGRP)              // 4 heads per group
#define GRP_PS   ((size_t)MTILES * HPS * N_)  // partialS floats per group
#define NO_      ((size_t)N_ * O_)        // out elements

// fp16 scratch (static device globals; allocation-free kernel_launch)
__device__ __half g_kh[(size_t)N_ * O_];
__device__ __half g_memsh[(size_t)H_ * M_ * D_];
__device__ __half g_Wkh[(size_t)H_ * O_ * D_];
__device__ __half g_Wvh[(size_t)H_ * O_ * D_];
__device__ __half g_Wfh[(size_t)O_ * H_ * O_];
__device__ __half g_memkeyh[(size_t)H_ * M_ * O_];   // exp3 (unnormalized)
__device__ __half g_memvalh[(size_t)H_ * M_ * O_];
__device__ __half g_GTh[(size_t)H_ * M_ * O_];       // [h][O][M]
__device__ __half g_atth[(size_t)H_ * N_ * M_];      // exp5 (unnormalized)
__device__ float  g_partialS[(size_t)NGRP * GRP_PS];     // 8 MB
__device__ float  g_partialS3[(size_t)MT3 * ROWS3];      // 256 KB
__device__ float  g_part6[(size_t)NGRP * NO_];           // 134 MB

// ---------------------------------------------------------------------------
__device__ __forceinline__ void cp_async16(uint32_t smem_addr, const void* gptr) {
    asm volatile("cp.async.cg.shared.global [%0], [%1], 16;\n"
                 :: "r"(smem_addr), "l"(gptr));
}
__device__ __forceinline__ void ldmatrix_x4(uint32_t& r0, uint32_t& r1,
                                            uint32_t& r2, uint32_t& r3,
                                            uint32_t addr) {
    asm volatile("ldmatrix.sync.aligned.m8n8.x4.shared.b16 {%0,%1,%2,%3}, [%4];"
                 : "=r"(r0), "=r"(r1), "=r"(r2), "=r"(r3) : "r"(addr));
}
__device__ __forceinline__ uint32_t mul_f16x2(uint32_t a, uint32_t b) {
    uint32_t r;
    asm("mul.f16x2 %0, %1, %2;" : "=r"(r) : "r"(a), "r"(b));
    return r;
}
__device__ __forceinline__ uint32_t h2bits(float lo, float hi) {
    __half2 h = __floats2half2_rn(lo, hi);
    return *reinterpret_cast<uint32_t*>(&h);
}

// ---------------------------------------------------------------------------
// fp32 -> fp16 convert (8 floats / thread)
// ---------------------------------------------------------------------------
__global__ void __launch_bounds__(256) cvt_f32_f16(
    const float4* __restrict__ in, uint2* __restrict__ out, int n8)
{
    int i = blockIdx.x * 256 + threadIdx.x;
    if (i < n8) {
        float4 a = in[2 * i];
        float4 b = in[2 * i + 1];
        uint2 o0, o1;
        o0.x = h2bits(a.x, a.y);
        o0.y = h2bits(a.z, a.w);
        o1.x = h2bits(b.x, b.y);
        o1.y = h2bits(b.z, b.w);
        out[2 * i] = o0;
        out[2 * i + 1] = o1;
    }
}

// ---------------------------------------------------------------------------
// out = p0 + p1 + p2 + p3 + bias (vectorized; n4 = N*O/4)
// ---------------------------------------------------------------------------
__global__ void __launch_bounds__(256) reduce_out(
    const float4* __restrict__ p, const float* __restrict__ bf,
    float4* __restrict__ out, int n4)
{
    int i = blockIdx.x * 256 + threadIdx.x;
    if (i < n4) {
        const size_t NO4 = NO_ / 4;
        float4 a = p[i];
        float4 b = p[NO4 + i];
        float4 c = p[2 * NO4 + i];
        float4 d = p[3 * NO4 + i];
        float4 bb = *reinterpret_cast<const float4*>(bf + (size_t)(i % (O_ / 4)) * 4);
        float4 o;
        o.x = a.x + b.x + c.x + d.x + bb.x;
        o.y = a.y + b.y + c.y + d.y + bb.y;
        o.z = a.z + b.z + c.z + d.z + bb.z;
        o.w = a.w + b.w + c.w + d.w + bb.w;
        out[i] = o;
    }
}

// ---------------------------------------------------------------------------
// fp16 tensor-core GEMM NT, fp32 accumulate:
//   C[m, n] = sum_k A[m, k] * B[n, k]  (+ bias[n])
// mode: 0 = fp32 out, 1 = fp16 out,
//       2 = fp16 exp(acc*colScale + bias - expShift) (fp32 __expf)
//           + deterministic row partial sums.
// kSplit>0: A/B indexed per head (aHead/bHead k-strides).
// rsPart: fused row-scale — CTA recomputes 1/sum for rsHeads x TBM rows into
//         smem (layout [t][hh][rsLd]); A fragments scaled in-loop (fp16 mul).
// csPart: fused col-scale — CTA recomputes 1/sum for TBN cols into smem.
// ---------------------------------------------------------------------------
__global__ void __launch_bounds__(256, 2) gemm_nt_f16(
    const __half* __restrict__ A, long long aHead, long long lda,
    const __half* __restrict__ B, long long bHead, long long ldb,
    void* __restrict__ Cv, long long cHead, long long ldc,
    const float* __restrict__ bias, long long biasHead,
    int K, int kSplit, int mode,
    float* __restrict__ partialS,
    const float* __restrict__ rsPart, int rsHeads, long long rsLd,
    int rsTiles, long long rsStride,
    const float* __restrict__ csPart, long long csLd,
    int csTiles, long long csStride,
    float expShift)
{
    const int z = blockIdx.z;
    if (kSplit == 0) {
        A += (long long)z * aHead;
        B += (long long)z * bHead;
    }
    if (bias) bias += (long long)z * biasHead;

    extern __shared__ __align__(16) char smraw[];
    const uint32_t smBase = (uint32_t)__cvta_generic_to_shared(smraw);
    const uint32_t BOFF = TBM * ROWB;
    float* scaleBuf = reinterpret_cast<float*>(smraw + NSTG * STGB);

    const int tid  = threadIdx.x;
    const int lane = tid & 31;
    const int warp = tid >> 5;
    const int g  = lane >> 2;
    const int tg = lane & 3;

    const int wm0 = (warp & 3) * 32;
    const int wn0 = (warp >> 2) * 64;

    const long long m0 = (long long)blockIdx.y * TBM;
    const long long n0 = (long long)blockIdx.x * TBN;

    // Fused scale recomputation (deterministic fixed-order sums).
    if (rsPart) {
        for (int idx = tid; idx < rsHeads * TBM; idx += 256) {
            const int hh = idx / TBM;
            const int rr = idx - hh * TBM;
            const long long base = ((long long)z * rsHeads + hh) * rsLd + m0 + rr;
            float s = 0.f;
            for (int t = 0; t < rsTiles; ++t) s += rsPart[(long long)t * rsStride + base];
            scaleBuf[idx] = 1.0f / s;
        }
    }
    if (csPart && tid < TBN) {
        const long long base = (long long)z * csLd + n0 + tid;
        float s = 0.f;
        for (int t = 0; t < csTiles; ++t) s += csPart[(long long)t * csStride + base];
        scaleBuf[tid] = 1.0f / s;
    }
    // published by the first mainloop __syncthreads (nIter >= 1 always here)

    const int pRow = tid >> 1;
    const int pCh  = (tid & 1) * 2;
    const uint32_t prodOff = (uint32_t)(pRow * ROWB + pCh * 16);

    const __half* aRowPtr = A + (m0 + pRow) * lda + pCh * 8;
    const __half* bRowPtr = B + (n0 + pRow) * ldb + pCh * 8;

    auto loadTile = [&](int kt, int stg) {
        const long long k0 = (long long)kt * TBK;
        long long kA, kB;
        if (kSplit > 0) {
            const long long kh = k0 / kSplit;
            const long long ko = k0 - kh * kSplit;
            kA = kh * aHead + ko;
            kB = kh * bHead + ko;
        } else {
            kA = k0; kB = k0;
        }
        const uint32_t ab = smBase + (uint32_t)stg * STGB + prodOff;
        const uint32_t bb = ab + BOFF;
#pragma unroll
        for (int c = 0; c < 2; ++c) {
            cp_async16(ab + c * 16, aRowPtr + kA + c * 8);
            cp_async16(bb + c * 16, bRowPtr + kB + c * 8);
        }
        asm volatile("cp.async.commit_group;\n" ::);
    };

    const int mat  = lane >> 3;
    const int row8 = lane & 7;
    uint32_t aOff[2], bOff[4];
#pragma unroll
    for (int i = 0; i < 2; ++i)
        aOff[i] = (uint32_t)((wm0 + i * 16 + (mat & 1) * 8 + row8) * ROWB
                             + (mat >> 1) * 16);
#pragma unroll
    for (int p = 0; p < 4; ++p)
        bOff[p] = (uint32_t)(BOFF + (wn0 + (2 * p + (mat >> 1)) * 8 + row8) * ROWB
                             + (mat & 1) * 16);

    float acc[2][8][4];
#pragma unroll
    for (int i = 0; i < 2; ++i)
#pragma unroll
        for (int j = 0; j < 8; ++j)
#pragma unroll
            for (int r = 0; r < 4; ++r) acc[i][j][r] = 0.f;

    uint32_t sreg[2][2];
    int lastKh = -1;

    const int nIter = K / TBK;
    loadTile(0, 0);
    if (nIter > 1) loadTile(1, 1);

    int stg = 0;
    for (int kt = 0; kt < nIter; ++kt) {
        if (kt + 1 < nIter) {
            asm volatile("cp.async.wait_group 1;\n" ::);
        } else {
            asm volatile("cp.async.wait_group 0;\n" ::);
        }
        __syncthreads();

        if (kt + 2 < nIter) {
            int ns = stg + 2; if (ns >= NSTG) ns -= NSTG;
            loadTile(kt + 2, ns);
        }

        if (rsPart) {
            const int kh = (int)(((long long)kt * TBK) / kSplit);
            if (kh != lastKh) {
                lastKh = kh;
#pragma unroll
                for (int i = 0; i < 2; ++i) {
                    const int lr = wm0 + i * 16 + g;
                    float s0 = scaleBuf[kh * TBM + lr];
                    float s1 = scaleBuf[kh * TBM + lr + 8];
                    sreg[i][0] = h2bits(s0, s0);
                    sreg[i][1] = h2bits(s1, s1);
                }
            }
        }

        const uint32_t base = smBase + (uint32_t)stg * STGB;
#pragma unroll
        for (int ks = 0; ks < 2; ++ks) {
            const uint32_t ksb = base + ks * 32;
            uint32_t af[2][4];
#pragma unroll
            for (int i = 0; i < 2; ++i)
                ldmatrix_x4(af[i][0], af[i][1], af[i][2], af[i][3], ksb + aOff[i]);
            if (rsPart) {
#pragma unroll
                for (int i = 0; i < 2; ++i) {
                    af[i][0] = mul_f16x2(af[i][0], sreg[i][0]);
                    af[i][1] = mul_f16x2(af[i][1], sreg[i][1]);
                    af[i][2] = mul_f16x2(af[i][2], sreg[i][0]);
                    af[i][3] = mul_f16x2(af[i][3], sreg[i][1]);
                }
            }
            uint32_t bf[8][2];
#pragma unroll
            for (int p = 0; p < 4; ++p)
                ldmatrix_x4(bf[2 * p][0], bf[2 * p][1],
                            bf[2 * p + 1][0], bf[2 * p + 1][1], ksb + bOff[p]);
#pragma unroll
            for (int i = 0; i < 2; ++i) {
#pragma unroll
                for (int j = 0; j < 8; ++j) {
                    asm volatile(
                        "mma.sync.aligned.m16n8k16.row.col.f32.f16.f16.f32 "
                        "{%0,%1,%2,%3}, {%4,%5,%6,%7}, {%8,%9}, {%0,%1,%2,%3};"
                        : "+f"(acc[i][j][0]), "+f"(acc[i][j][1]),
                          "+f"(acc[i][j][2]), "+f"(acc[i][j][3])
                        : "r"(af[i][0]), "r"(af[i][1]), "r"(af[i][2]), "r"(af[i][3]),
                          "r"(bf[j][0]), "r"(bf[j][1]));
                }
            }
        }
        ++stg; if (stg == NSTG) stg = 0;
    }

    const long long cBase = (long long)z * cHead;

    if (mode == 2) {
        __half* C = (__half*)Cv + cBase;
        float rsum[2][2] = {{0.f, 0.f}, {0.f, 0.f}};
#pragma unroll
        for (int i = 0; i < 2; ++i) {
            const long long r0 = m0 + wm0 + i * 16 + g;
#pragma unroll
            for (int j = 0; j < 8; ++j) {
                const int ccl = wn0 + j * 8 + 2 * tg;
                const long long cc = n0 + ccl;
                float a00 = acc[i][j][0], a01 = acc[i][j][1];
                float a10 = acc[i][j][2], a11 = acc[i][j][3];
                if (csPart) {
                    float s0 = scaleBuf[ccl], s1 = scaleBuf[ccl + 1];
                    a00 *= s0; a01 *= s1; a10 *= s0; a11 *= s1;
                }
                if (bias) {
                    float b0 = bias[cc], b1 = bias[cc + 1];
                    a00 += b0; a01 += b1; a10 += b0; a11 += b1;
                }
                float e00 = __expf(a00 - expShift);
                float e01 = __expf(a01 - expShift);
                float e10 = __expf(a10 - expShift);
                float e11 = __expf(a11 - expShift);
                rsum[i][0] += e00 + e01;
                rsum[i][1] += e10 + e11;
                *reinterpret_cast<uint32_t*>(C + r0 * ldc + cc) = h2bits(e00, e01);
                *reinterpret_cast<uint32_t*>(C + (r0 + 8) * ldc + cc) = h2bits(e10, e11);
            }
        }
#pragma unroll
        for (int i = 0; i < 2; ++i) {
#pragma unroll
            for (int hh = 0; hh < 2; ++hh) {
                rsum[i][hh] += __shfl_xor_sync(0xffffffffu, rsum[i][hh], 1);
                rsum[i][hh] += __shfl_xor_sync(0xffffffffu, rsum[i][hh], 2);
            }
        }
        float* sbuf = reinterpret_cast<float*>(smraw);
        __syncthreads();
        if (tg == 0) {
#pragma unroll
            for (int i = 0; i < 2; ++i) {
                sbuf[warp * 32 + 16 * i + g]     = rsum[i][0];
                sbuf[warp * 32 + 16 * i + g + 8] = rsum[i][1];
            }
        }
        __syncthreads();
        if (tid < TBM) {
            const int wq = tid >> 5;
            const int lr = tid & 31;
            const float s = sbuf[wq * 32 + lr] + sbuf[(wq + 4) * 32 + lr];
            const long long rows = (long long)gridDim.y * TBM;
            partialS[((long long)blockIdx.x * gridDim.z + z) * rows + m0 + tid] = s;
        }
        return;
    }

#pragma unroll
    for (int i = 0; i < 2; ++i) {
        const long long r0 = m0 + wm0 + i * 16 + g;
#pragma unroll
        for (int j = 0; j < 8; ++j) {
            const long long cc = n0 + wn0 + j * 8 + 2 * tg;
            float b0 = 0.f, b1 = 0.f;
            if (bias) { b0 = bias[cc]; b1 = bias[cc + 1]; }
            float v00 = acc[i][j][0] + b0, v01 = acc[i][j][1] + b1;
            float v10 = acc[i][j][2] + b0, v11 = acc[i][j][3] + b1;
            if (mode == 1) {
                __half* C = (__half*)Cv + cBase;
                *reinterpret_cast<uint32_t*>(C + r0 * ldc + cc) = h2bits(v00, v01);
                *reinterpret_cast<uint32_t*>(C + (r0 + 8) * ldc + cc) = h2bits(v10, v11);
            } else {
                float* C = (float*)Cv + cBase;
                *reinterpret_cast<float2*>(C + r0 * ldc + cc) = make_float2(v00, v01);
                *reinterpret_cast<float2*>(C + (r0 + 8) * ldc + cc) = make_float2(v10, v11);
            }
        }
    }
}

// ---------------------------------------------------------------------------
// Launch
// ---------------------------------------------------------------------------
extern "C" void kernel_launch(void* const* d_in, const int* in_sizes, int n_in,
                              void* d_out, int out_size)
{
    const float* k_in = (const float*)d_in[0];   // [N, O]
    const float* mems = (const float*)d_in[1];   // [H, M, D]
    const float* Wk   = (const float*)d_in[2];   // [H, O, D]
    const float* bk   = (const float*)d_in[3];   // [H, O]
    const float* Wv   = (const float*)d_in[4];   // [H, O, D]
    const float* bv   = (const float*)d_in[5];   // [H, O]
    const float* Wf   = (const float*)d_in[6];   // [O, H*O]
    const float* bf   = (const float*)d_in[7];   // [O]
    float* out = (float*)d_out;                  // [N, O]

    cudaFuncSetAttribute(gemm_nt_f16,
                         cudaFuncAttributeMaxDynamicSharedMemorySize, SMEM_DYN);

    static cudaStream_t sB = nullptr, sC = nullptr;
    static cudaEvent_t eFork, eMems, eK, eWf, eG6;
    static cudaEvent_t ev4[NGRP];
    if (sB == nullptr) {
        cudaStreamCreateWithFlags(&sB, cudaStreamNonBlocking);
        cudaStreamCreateWithFlags(&sC, cudaStreamNonBlocking);
        cudaEventCreateWithFlags(&eFork, cudaEventDisableTiming);
        cudaEventCreateWithFlags(&eMems, cudaEventDisableTiming);
        cudaEventCreateWithFlags(&eK,    cudaEventDisableTiming);
        cudaEventCreateWithFlags(&eWf,   cudaEventDisableTiming);
        cudaEventCreateWithFlags(&eG6,   cudaEventDisableTiming);
        for (int i = 0; i < NGRP; ++i)
            cudaEventCreateWithFlags(&ev4[i], cudaEventDisableTiming);
    }

    __half *kh, *memsh, *Wkh, *Wvh, *Wfh, *memkeyh, *memvalh, *GTh, *atth;
    float *partialS, *partialS3, *part6;
    cudaGetSymbolAddress((void**)&kh,        g_kh);
    cudaGetSymbolAddress((void**)&memsh,     g_memsh);
    cudaGetSymbolAddress((void**)&Wkh,       g_Wkh);
    cudaGetSymbolAddress((void**)&Wvh,       g_Wvh);
    cudaGetSymbolAddress((void**)&Wfh,       g_Wfh);
    cudaGetSymbolAddress((void**)&memkeyh,   g_memkeyh);
    cudaGetSymbolAddress((void**)&memvalh,   g_memvalh);
    cudaGetSymbolAddress((void**)&GTh,       g_GTh);
    cudaGetSymbolAddress((void**)&atth,      g_atth);
    cudaGetSymbolAddress((void**)&partialS,  g_partialS);
    cudaGetSymbolAddress((void**)&partialS3, g_partialS3);
    cudaGetSymbolAddress((void**)&part6,     g_part6);

    const long long MD = (long long)M_ * D_;
    const long long OD = (long long)O_ * D_;
    const long long MO = (long long)M_ * O_;
    const long long NM = (long long)N_ * M_;

    auto cvtOn = [&](cudaStream_t s, const float* src, __half* dst, long long n) {
        int n8 = (int)(n / 8);
        cvt_f32_f16<<<(n8 + 255) / 256, 256, 0, s>>>(
            (const float4*)src, (uint2*)dst, n8);
    };

    // ---- fork ----
    cudaEventRecord(eFork, 0);
    cudaStreamWaitEvent(sB, eFork, 0);
    cudaStreamWaitEvent(sC, eFork, 0);

    // sC: cvt k, cvt Wf
    cvtOn(sC, k_in, kh, (long long)N_ * O_);
    cudaEventRecord(eK, sC);
    cvtOn(sC, Wf, Wfh, (long long)O_ * H_ * O_);
    cudaEventRecord(eWf, sC);

    // spine: cvt mems, cvt Wk
    cvtOn(0, mems, memsh, (long long)H_ * M_ * D_);
    cudaEventRecord(eMems, 0);
    cvtOn(0, Wk, Wkh, (long long)H_ * O_ * D_);

    // sB: cvt Wv -> GEMM2 -> GEMM3b
    cvtOn(sB, Wv, Wvh, (long long)H_ * O_ * D_);
    cudaStreamWaitEvent(sB, eMems, 0);
    {
        dim3 grid(O_ / TBN, M_ / TBM, H_);
        gemm_nt_f16<<<grid, 256, SMEM_DYN, sB>>>(memsh, MD, D_, Wvh, OD, D_,
                                                 memvalh, MO, O_, bv, O_, D_, 0, 1,
                                                 nullptr,
                                                 nullptr, 0, 0, 0, 0,
                                                 nullptr, 0, 0, 0, 0.f);
    }
    cudaStreamWaitEvent(sB, eWf, 0);
    {
        dim3 grid(M_ / TBN, O_ / TBM, H_);
        gemm_nt_f16<<<grid, 256, SMEM_DYN, sB>>>(Wfh, O_, (long long)H_ * O_,
                                                 memvalh, MO, O_,
                                                 GTh, MO, M_, nullptr, 0, O_, 0, 1,
                                                 nullptr,
                                                 nullptr, 0, 0, 0, 0,
                                                 nullptr, 0, 0, 0, 0.f);
    }

    // spine: GEMM1 exp mode (exp(logit + bk), row partial sums)
    {
        dim3 grid(O_ / TBN, M_ / TBM, H_);
        gemm_nt_f16<<<grid, 256, SMEM_DYN>>>(memsh, MD, D_, Wkh, OD, D_,
                                             memkeyh, MO, O_, bk, O_, D_, 0, 2,
                                             partialS3,
                                             nullptr, 0, 0, 0, 0,
                                             nullptr, 0, 0, 0, 0.0f);
    }

    // spine: GEMM4 per head group; GEMM6 split g consumes on sB (L2-warm)
    cudaStreamWaitEvent(0, eK, 0);
    for (int gI = 0; gI < NGRP; ++gI) {
        {
            dim3 grid(M_ / TBN, N_ / TBM, HPS);
            gemm_nt_f16<<<grid, 256, SMEM_DYN>>>(
                kh, 0, O_,
                memkeyh + (long long)gI * HPS * MO, MO, O_,
                atth + (long long)gI * HPS * NM, NM, M_,
                nullptr, 0, O_, 0, 2,
                partialS + (size_t)gI * GRP_PS,
                nullptr, 0, 0, 0, 0,
                partialS3 + (long long)gI * HPS * M_, M_, MT3, ROWS3,
                4.0f);
        }
        cudaEventRecord(ev4[gI], 0);
        cudaStreamWaitEvent(sB, ev4[gI], 0);
        {
            dim3 grid(O_ / TBN, N_ / TBM, 1);
            gemm_nt_f16<<<grid, 256, SMEM_DYN, sB>>>(
                atth + (long long)gI * HPS * NM, NM, M_,
                GTh + (long long)gI * HPS * MO, MO, M_,
                part6 + (size_t)gI * NO_, 0, O_,
                nullptr, 0,
                HPS * M_, M_, 0,
                nullptr,
                partialS + (size_t)gI * GRP_PS, HPS, N_, MTILES,
                (long long)HPS * N_,
                nullptr, 0, 0, 0, 0.f);
        }
    }
    cudaEventRecord(eG6, sB);

    // join: reduce partials + bias
    cudaStreamWaitEvent(0, eG6, 0);
    {
        int n4 = (int)(NO_ / 4);
        reduce_out<<<(n4 + 255) / 256, 256>>>((const float4*)part6, bf,
                                              (float4*)out, n4);
    }
}

// round 15
// speedup vs baseline: 1.0368x; 1.0368x over previous
#include <cuda_runtime.h>
#include <cuda_fp16.h>
#include <cstdint>
#include <cstddef>

// ---------------------------------------------------------------------------
// MultiHeadMemory: H=16, M=1024, D=512, O=512, N=16384
// fp16 mma.sync engine at the legacy-HMMA roofline (~288 TF/s).
// R15: best-of configuration — R12 serial schedule (single GEMM4, single
// split-K=4 GEMM6, 98.8% wave fill) + R13 fused sum_inv recomputes + fp32
// __expf epilogue numerics. No concurrent tensor kernels (R10/R14 lesson).
//
// spine (s0): cvt mems, cvt Wk -> GEMM1(exp) -> [eK] GEMM4(exp, csFuse)
//             -> [e3b] GEMM6(rsFuse, split-K=4) -> reduce(+bias)
// sB:  [fork] cvt Wv -> [eMems] GEMM2 -> [eWf] GEMM3b -> e3b
// sC:  [fork] cvt k -> eK ; cvt Wf -> eWf
// ---------------------------------------------------------------------------

#define H_  16
#define M_  1024
#define D_  512
#define O_  512
#define N_  16384

#define TBM 128
#define TBN 128
#define TBK 32          // halves per k-tile
#define ROWB 80         // bytes per SMEM row: 64 B data + 16 B pad
#define NSTG 3
#define STGB (2 * TBM * ROWB)            // A+B per stage = 20480 B
#define SCALEBUF 2048                    // smem bytes for fused scale buffers
#define SMEM_DYN (NSTG * STGB + SCALEBUF)    // 63488 B

#define MTILES   8                        // GEMM4 col tiles (M_/TBN)
#define ROWS_TOT (H_ * N_)                // 262144 softmax5 rows
#define MT3      4                        // GEMM1 col tiles (O_/TBN)
#define ROWS3    (H_ * M_)                // 16384 softmax3 rows
#define SPLIT6   4                        // GEMM6 head-group splits
#define HPS      (H_ / SPLIT6)            // 4 heads per split
#define NO_      ((size_t)N_ * O_)        // out elements

// fp16 scratch (static device globals; allocation-free kernel_launch)
__device__ __half g_kh[(size_t)N_ * O_];
__device__ __half g_memsh[(size_t)H_ * M_ * D_];
__device__ __half g_Wkh[(size_t)H_ * O_ * D_];
__device__ __half g_Wvh[(size_t)H_ * O_ * D_];
__device__ __half g_Wfh[(size_t)O_ * H_ * O_];
__device__ __half g_memkeyh[(size_t)H_ * M_ * O_];   // exp3 (unnormalized)
__device__ __half g_memvalh[(size_t)H_ * M_ * O_];
__device__ __half g_GTh[(size_t)H_ * M_ * O_];       // [h][O][M]
__device__ __half g_atth[(size_t)H_ * N_ * M_];      // exp5 (unnormalized)
__device__ float  g_partialS[(size_t)MTILES * ROWS_TOT]; // 8 MB
__device__ float  g_partialS3[(size_t)MT3 * ROWS3];      // 256 KB
__device__ float  g_part6[(size_t)SPLIT6 * NO_];         // 134 MB

// ---------------------------------------------------------------------------
__device__ __forceinline__ void cp_async16(uint32_t smem_addr, const void* gptr) {
    asm volatile("cp.async.cg.shared.global [%0], [%1], 16;\n"
                 :: "r"(smem_addr), "l"(gptr));
}
__device__ __forceinline__ void ldmatrix_x4(uint32_t& r0, uint32_t& r1,
                                            uint32_t& r2, uint32_t& r3,
                                            uint32_t addr) {
    asm volatile("ldmatrix.sync.aligned.m8n8.x4.shared.b16 {%0,%1,%2,%3}, [%4];"
                 : "=r"(r0), "=r"(r1), "=r"(r2), "=r"(r3) : "r"(addr));
}
__device__ __forceinline__ uint32_t mul_f16x2(uint32_t a, uint32_t b) {
    uint32_t r;
    asm("mul.f16x2 %0, %1, %2;" : "=r"(r) : "r"(a), "r"(b));
    return r;
}
__device__ __forceinline__ uint32_t h2bits(float lo, float hi) {
    __half2 h = __floats2half2_rn(lo, hi);
    return *reinterpret_cast<uint32_t*>(&h);
}

// ---------------------------------------------------------------------------
// fp32 -> fp16 convert (8 floats / thread)
// ---------------------------------------------------------------------------
__global__ void __launch_bounds__(256) cvt_f32_f16(
    const float4* __restrict__ in, uint2* __restrict__ out, int n8)
{
    int i = blockIdx.x * 256 + threadIdx.x;
    if (i < n8) {
        float4 a = in[2 * i];
        float4 b = in[2 * i + 1];
        uint2 o0, o1;
        o0.x = h2bits(a.x, a.y);
        o0.y = h2bits(a.z, a.w);
        o1.x = h2bits(b.x, b.y);
        o1.y = h2bits(b.z, b.w);
        out[2 * i] = o0;
        out[2 * i + 1] = o1;
    }
}

// ---------------------------------------------------------------------------
// out = p0 + p1 + p2 + p3 + bias (vectorized; n4 = N*O/4)
// ---------------------------------------------------------------------------
__global__ void __launch_bounds__(256) reduce_out(
    const float4* __restrict__ p, const float* __restrict__ bf,
    float4* __restrict__ out, int n4)
{
    int i = blockIdx.x * 256 + threadIdx.x;
    if (i < n4) {
        const size_t NO4 = NO_ / 4;
        float4 a = p[i];
        float4 b = p[NO4 + i];
        float4 c = p[2 * NO4 + i];
        float4 d = p[3 * NO4 + i];
        float4 bb = *reinterpret_cast<const float4*>(bf + (size_t)(i % (O_ / 4)) * 4);
        float4 o;
        o.x = a.x + b.x + c.x + d.x + bb.x;
        o.y = a.y + b.y + c.y + d.y + bb.y;
        o.z = a.z + b.z + c.z + d.z + bb.z;
        o.w = a.w + b.w + c.w + d.w + bb.w;
        out[i] = o;
    }
}

// ---------------------------------------------------------------------------
// fp16 tensor-core GEMM NT, fp32 accumulate:
//   C[m, n] = sum_k A[m, k] * B[n, k]  (+ bias[n])
// mode: 0 = fp32 out, 1 = fp16 out,
//       2 = fp16 exp(acc*colScale + bias - expShift) (fp32 __expf)
//           + deterministic row partial sums.
// kSplit>0: A/B indexed per head (aHead/bHead k-strides); blockIdx.z offsets
//           A/B by aZ/bZ (split-K by head groups).
// rsPart: fused row-scale — CTA recomputes 1/sum for rsHeads x TBM rows into
//         smem; A fragments scaled in-loop (fp16 mul).
// csPart: fused col-scale — CTA recomputes 1/sum for TBN cols into smem;
//         applied to accumulators in the mode-2 epilogue.
// ---------------------------------------------------------------------------
__global__ void __launch_bounds__(256, 2) gemm_nt_f16(
    const __half* __restrict__ A, long long aHead, long long lda,
    const __half* __restrict__ B, long long bHead, long long ldb,
    void* __restrict__ Cv, long long cHead, long long ldc,
    const float* __restrict__ bias, long long biasHead,
    int K, int kSplit, int mode,
    float* __restrict__ partialS,
    const float* __restrict__ rsPart, int rsHeads, long long rsLd,
    int rsTiles, long long rsStride,
    const float* __restrict__ csPart, long long csLd,
    int csTiles, long long csStride,
    long long aZ, long long bZ, float expShift)
{
    const int z = blockIdx.z;
    if (kSplit == 0) {
        A += (long long)z * aHead;
        B += (long long)z * bHead;
    } else {
        A += (long long)z * aZ;
        B += (long long)z * bZ;
    }
    if (bias) bias += (long long)z * biasHead;

    extern __shared__ __align__(16) char smraw[];
    const uint32_t smBase = (uint32_t)__cvta_generic_to_shared(smraw);
    const uint32_t BOFF = TBM * ROWB;
    float* scaleBuf = reinterpret_cast<float*>(smraw + NSTG * STGB);

    const int tid  = threadIdx.x;
    const int lane = tid & 31;
    const int warp = tid >> 5;
    const int g  = lane >> 2;
    const int tg = lane & 3;

    const int wm0 = (warp & 3) * 32;
    const int wn0 = (warp >> 2) * 64;

    const long long m0 = (long long)blockIdx.y * TBM;
    const long long n0 = (long long)blockIdx.x * TBN;

    // Fused scale recomputation (deterministic fixed-order sums).
    if (rsPart) {
        for (int idx = tid; idx < rsHeads * TBM; idx += 256) {
            const int hh = idx / TBM;
            const int rr = idx - hh * TBM;
            const long long base = ((long long)z * rsHeads + hh) * rsLd + m0 + rr;
            float s = 0.f;
            for (int t = 0; t < rsTiles; ++t) s += rsPart[(long long)t * rsStride + base];
            scaleBuf[idx] = 1.0f / s;
        }
    }
    if (csPart && tid < TBN) {
        const long long base = (long long)z * csLd + n0 + tid;
        float s = 0.f;
        for (int t = 0; t < csTiles; ++t) s += csPart[(long long)t * csStride + base];
        scaleBuf[tid] = 1.0f / s;
    }
    // published by the first mainloop __syncthreads (nIter >= 1 always here)

    const int pRow = tid >> 1;
    const int pCh  = (tid & 1) * 2;
    const uint32_t prodOff = (uint32_t)(pRow * ROWB + pCh * 16);

    const __half* aRowPtr = A + (m0 + pRow) * lda + pCh * 8;
    const __half* bRowPtr = B + (n0 + pRow) * ldb + pCh * 8;

    auto loadTile = [&](int kt, int stg) {
        const long long k0 = (long long)kt * TBK;
        long long kA, kB;
        if (kSplit > 0) {
            const long long kh = k0 / kSplit;
            const long long ko = k0 - kh * kSplit;
            kA = kh * aHead + ko;
            kB = kh * bHead + ko;
        } else {
            kA = k0; kB = k0;
        }
        const uint32_t ab = smBase + (uint32_t)stg * STGB + prodOff;
        const uint32_t bb = ab + BOFF;
#pragma unroll
        for (int c = 0; c < 2; ++c) {
            cp_async16(ab + c * 16, aRowPtr + kA + c * 8);
            cp_async16(bb + c * 16, bRowPtr + kB + c * 8);
        }
        asm volatile("cp.async.commit_group;\n" ::);
    };

    const int mat  = lane >> 3;
    const int row8 = lane & 7;
    uint32_t aOff[2], bOff[4];
#pragma unroll
    for (int i = 0; i < 2; ++i)
        aOff[i] = (uint32_t)((wm0 + i * 16 + (mat & 1) * 8 + row8) * ROWB
                             + (mat >> 1) * 16);
#pragma unroll
    for (int p = 0; p < 4; ++p)
        bOff[p] = (uint32_t)(BOFF + (wn0 + (2 * p + (mat >> 1)) * 8 + row8) * ROWB
                             + (mat & 1) * 16);

    float acc[2][8][4];
#pragma unroll
    for (int i = 0; i < 2; ++i)
#pragma unroll
        for (int j = 0; j < 8; ++j)
#pragma unroll
            for (int r = 0; r < 4; ++r) acc[i][j][r] = 0.f;

    uint32_t sreg[2][2];
    int lastKh = -1;

    const int nIter = K / TBK;
    loadTile(0, 0);
    if (nIter > 1) loadTile(1, 1);

    int stg = 0;
    for (int kt = 0; kt < nIter; ++kt) {
        if (kt + 1 < nIter) {
            asm volatile("cp.async.wait_group 1;\n" ::);
        } else {
            asm volatile("cp.async.wait_group 0;\n" ::);
        }
        __syncthreads();

        if (kt + 2 < nIter) {
            int ns = stg + 2; if (ns >= NSTG) ns -= NSTG;
            loadTile(kt + 2, ns);
        }

        if (rsPart) {
            const int kh = (int)(((long long)kt * TBK) / kSplit);
            if (kh != lastKh) {
                lastKh = kh;
#pragma unroll
                for (int i = 0; i < 2; ++i) {
                    const int lr = wm0 + i * 16 + g;
                    float s0 = scaleBuf[kh * TBM + lr];
                    float s1 = scaleBuf[kh * TBM + lr + 8];
                    sreg[i][0] = h2bits(s0, s0);
                    sreg[i][1] = h2bits(s1, s1);
                }
            }
        }

        const uint32_t base = smBase + (uint32_t)stg * STGB;
#pragma unroll
        for (int ks = 0; ks < 2; ++ks) {
            const uint32_t ksb = base + ks * 32;
            uint32_t af[2][4];
#pragma unroll
            for (int i = 0; i < 2; ++i)
                ldmatrix_x4(af[i][0], af[i][1], af[i][2], af[i][3], ksb + aOff[i]);
            if (rsPart) {
#pragma unroll
                for (int i = 0; i < 2; ++i) {
                    af[i][0] = mul_f16x2(af[i][0], sreg[i][0]);
                    af[i][1] = mul_f16x2(af[i][1], sreg[i][1]);
                    af[i][2] = mul_f16x2(af[i][2], sreg[i][0]);
                    af[i][3] = mul_f16x2(af[i][3], sreg[i][1]);
                }
            }
            uint32_t bf[8][2];
#pragma unroll
            for (int p = 0; p < 4; ++p)
                ldmatrix_x4(bf[2 * p][0], bf[2 * p][1],
                            bf[2 * p + 1][0], bf[2 * p + 1][1], ksb + bOff[p]);
#pragma unroll
            for (int i = 0; i < 2; ++i) {
#pragma unroll
                for (int j = 0; j < 8; ++j) {
                    asm volatile(
                        "mma.sync.aligned.m16n8k16.row.col.f32.f16.f16.f32 "
                        "{%0,%1,%2,%3}, {%4,%5,%6,%7}, {%8,%9}, {%0,%1,%2,%3};"
                        : "+f"(acc[i][j][0]), "+f"(acc[i][j][1]),
                          "+f"(acc[i][j][2]), "+f"(acc[i][j][3])
                        : "r"(af[i][0]), "r"(af[i][1]), "r"(af[i][2]), "r"(af[i][3]),
                          "r"(bf[j][0]), "r"(bf[j][1]));
                }
            }
        }
        ++stg; if (stg == NSTG) stg = 0;
    }

    const long long cBase = (long long)z * cHead;

    if (mode == 2) {
        __half* C = (__half*)Cv + cBase;
        float rsum[2][2] = {{0.f, 0.f}, {0.f, 0.f}};
#pragma unroll
        for (int i = 0; i < 2; ++i) {
            const long long r0 = m0 + wm0 + i * 16 + g;
#pragma unroll
            for (int j = 0; j < 8; ++j) {
                const int ccl = wn0 + j * 8 + 2 * tg;
                const long long cc = n0 + ccl;
                float a00 = acc[i][j][0], a01 = acc[i][j][1];
                float a10 = acc[i][j][2], a11 = acc[i][j][3];
                if (csPart) {
                    float s0 = scaleBuf[ccl], s1 = scaleBuf[ccl + 1];
                    a00 *= s0; a01 *= s1; a10 *= s0; a11 *= s1;
                }
                if (bias) {
                    float b0 = bias[cc], b1 = bias[cc + 1];
                    a00 += b0; a01 += b1; a10 += b0; a11 += b1;
                }
                float e00 = __expf(a00 - expShift);
                float e01 = __expf(a01 - expShift);
                float e10 = __expf(a10 - expShift);
                float e11 = __expf(a11 - expShift);
                rsum[i][0] += e00 + e01;
                rsum[i][1] += e10 + e11;
                *reinterpret_cast<uint32_t*>(C + r0 * ldc + cc) = h2bits(e00, e01);
                *reinterpret_cast<uint32_t*>(C + (r0 + 8) * ldc + cc) = h2bits(e10, e11);
            }
        }
#pragma unroll
        for (int i = 0; i < 2; ++i) {
#pragma unroll
            for (int hh = 0; hh < 2; ++hh) {
                rsum[i][hh] += __shfl_xor_sync(0xffffffffu, rsum[i][hh], 1);
                rsum[i][hh] += __shfl_xor_sync(0xffffffffu, rsum[i][hh], 2);
            }
        }
        float* sbuf = reinterpret_cast<float*>(smraw);
        __syncthreads();
        if (tg == 0) {
#pragma unroll
            for (int i = 0; i < 2; ++i) {
                sbuf[warp * 32 + 16 * i + g]     = rsum[i][0];
                sbuf[warp * 32 + 16 * i + g + 8] = rsum[i][1];
            }
        }
        __syncthreads();
        if (tid < TBM) {
            const int wq = tid >> 5;
            const int lr = tid & 31;
            const float s = sbuf[wq * 32 + lr] + sbuf[(wq + 4) * 32 + lr];
            const long long rows = (long long)gridDim.y * TBM;
            partialS[((long long)blockIdx.x * gridDim.z + z) * rows + m0 + tid] = s;
        }
        return;
    }

#pragma unroll
    for (int i = 0; i < 2; ++i) {
        const long long r0 = m0 + wm0 + i * 16 + g;
#pragma unroll
        for (int j = 0; j < 8; ++j) {
            const long long cc = n0 + wn0 + j * 8 + 2 * tg;
            float b0 = 0.f, b1 = 0.f;
            if (bias) { b0 = bias[cc]; b1 = bias[cc + 1]; }
            float v00 = acc[i][j][0] + b0, v01 = acc[i][j][1] + b1;
            float v10 = acc[i][j][2] + b0, v11 = acc[i][j][3] + b1;
            if (mode == 1) {
                __half* C = (__half*)Cv + cBase;
                *reinterpret_cast<uint32_t*>(C + r0 * ldc + cc) = h2bits(v00, v01);
                *reinterpret_cast<uint32_t*>(C + (r0 + 8) * ldc + cc) = h2bits(v10, v11);
            } else {
                float* C = (float*)Cv + cBase;
                *reinterpret_cast<float2*>(C + r0 * ldc + cc) = make_float2(v00, v01);
                *reinterpret_cast<float2*>(C + (r0 + 8) * ldc + cc) = make_float2(v10, v11);
            }
        }
    }
}

// ---------------------------------------------------------------------------
// Launch
// ---------------------------------------------------------------------------
extern "C" void kernel_launch(void* const* d_in, const int* in_sizes, int n_in,
                              void* d_out, int out_size)
{
    const float* k_in = (const float*)d_in[0];   // [N, O]
    const float* mems = (const float*)d_in[1];   // [H, M, D]
    const float* Wk   = (const float*)d_in[2];   // [H, O, D]
    const float* bk   = (const float*)d_in[3];   // [H, O]
    const float* Wv   = (const float*)d_in[4];   // [H, O, D]
    const float* bv   = (const float*)d_in[5];   // [H, O]
    const float* Wf   = (const float*)d_in[6];   // [O, H*O]
    const float* bf   = (const float*)d_in[7];   // [O]
    float* out = (float*)d_out;                  // [N, O]

    cudaFuncSetAttribute(gemm_nt_f16,
                         cudaFuncAttributeMaxDynamicSharedMemorySize, SMEM_DYN);

    static cudaStream_t sB = nullptr, sC = nullptr;
    static cudaEvent_t eFork, eMems, eK, eWf, e3b;
    if (sB == nullptr) {
        cudaStreamCreateWithFlags(&sB, cudaStreamNonBlocking);
        cudaStreamCreateWithFlags(&sC, cudaStreamNonBlocking);
        cudaEventCreateWithFlags(&eFork, cudaEventDisableTiming);
        cudaEventCreateWithFlags(&eMems, cudaEventDisableTiming);
        cudaEventCreateWithFlags(&eK,    cudaEventDisableTiming);
        cudaEventCreateWithFlags(&eWf,   cudaEventDisableTiming);
        cudaEventCreateWithFlags(&e3b,   cudaEventDisableTiming);
    }

    __half *kh, *memsh, *Wkh, *Wvh, *Wfh, *memkeyh, *memvalh, *GTh, *atth;
    float *partialS, *partialS3, *part6;
    cudaGetSymbolAddress((void**)&kh,        g_kh);
    cudaGetSymbolAddress((void**)&memsh,     g_memsh);
    cudaGetSymbolAddress((void**)&Wkh,       g_Wkh);
    cudaGetSymbolAddress((void**)&Wvh,       g_Wvh);
    cudaGetSymbolAddress((void**)&Wfh,       g_Wfh);
    cudaGetSymbolAddress((void**)&memkeyh,   g_memkeyh);
    cudaGetSymbolAddress((void**)&memvalh,   g_memvalh);
    cudaGetSymbolAddress((void**)&GTh,       g_GTh);
    cudaGetSymbolAddress((void**)&atth,      g_atth);
    cudaGetSymbolAddress((void**)&partialS,  g_partialS);
    cudaGetSymbolAddress((void**)&partialS3, g_partialS3);
    cudaGetSymbolAddress((void**)&part6,     g_part6);

    const long long MD = (long long)M_ * D_;
    const long long OD = (long long)O_ * D_;
    const long long MO = (long long)M_ * O_;
    const long long NM = (long long)N_ * M_;

    auto cvtOn = [&](cudaStream_t s, const float* src, __half* dst, long long n) {
        int n8 = (int)(n / 8);
        cvt_f32_f16<<<(n8 + 255) / 256, 256, 0, s>>>(
            (const float4*)src, (uint2*)dst, n8);
    };

    // ---- fork ----
    cudaEventRecord(eFork, 0);
    cudaStreamWaitEvent(sB, eFork, 0);
    cudaStreamWaitEvent(sC, eFork, 0);

    // sC: cvt k, cvt Wf
    cvtOn(sC, k_in, kh, (long long)N_ * O_);
    cudaEventRecord(eK, sC);
    cvtOn(sC, Wf, Wfh, (long long)O_ * H_ * O_);
    cudaEventRecord(eWf, sC);

    // spine: cvt mems, cvt Wk
    cvtOn(0, mems, memsh, (long long)H_ * M_ * D_);
    cudaEventRecord(eMems, 0);
    cvtOn(0, Wk, Wkh, (long long)H_ * O_ * D_);

    // sB: cvt Wv -> GEMM2 -> GEMM3b
    cvtOn(sB, Wv, Wvh, (long long)H_ * O_ * D_);
    cudaStreamWaitEvent(sB, eMems, 0);
    {
        dim3 grid(O_ / TBN, M_ / TBM, H_);
        gemm_nt_f16<<<grid, 256, SMEM_DYN, sB>>>(memsh, MD, D_, Wvh, OD, D_,
                                                 memvalh, MO, O_, bv, O_, D_, 0, 1,
                                                 nullptr,
                                                 nullptr, 0, 0, 0, 0,
                                                 nullptr, 0, 0, 0,
                                                 0, 0, 0.f);
    }
    cudaStreamWaitEvent(sB, eWf, 0);
    {
        dim3 grid(M_ / TBN, O_ / TBM, H_);
        gemm_nt_f16<<<grid, 256, SMEM_DYN, sB>>>(Wfh, O_, (long long)H_ * O_,
                                                 memvalh, MO, O_,
                                                 GTh, MO, M_, nullptr, 0, O_, 0, 1,
                                                 nullptr,
                                                 nullptr, 0, 0, 0, 0,
                                                 nullptr, 0, 0, 0,
                                                 0, 0, 0.f);
    }
    cudaEventRecord(e3b, sB);

    // spine: GEMM1 exp mode (exp(logit + bk), row partial sums)
    {
        dim3 grid(O_ / TBN, M_ / TBM, H_);
        gemm_nt_f16<<<grid, 256, SMEM_DYN>>>(memsh, MD, D_, Wkh, OD, D_,
                                             memkeyh, MO, O_, bk, O_, D_, 0, 2,
                                             partialS3,
                                             nullptr, 0, 0, 0, 0,
                                             nullptr, 0, 0, 0,
                                             0, 0, 0.0f);
    }

    // spine: GEMM4 exp mode, col-scale fused from partialS3 (invS3 recompute)
    cudaStreamWaitEvent(0, eK, 0);
    {
        dim3 grid(M_ / TBN, N_ / TBM, H_);
        gemm_nt_f16<<<grid, 256, SMEM_DYN>>>(kh, 0, O_, memkeyh, MO, O_,
                                             atth, NM, M_, nullptr, 0, O_, 0, 2,
                                             partialS,
                                             nullptr, 0, 0, 0, 0,
                                             partialS3, M_, MT3, ROWS3,
                                             0, 0, 4.0f);
    }

    // join: GEMM6 split-K=4 by head group, row-scale fused from partialS
    cudaStreamWaitEvent(0, e3b, 0);
    {
        dim3 grid(O_ / TBN, N_ / TBM, SPLIT6);
        gemm_nt_f16<<<grid, 256, SMEM_DYN>>>(atth, NM, M_, GTh, MO, M_,
                                             part6, (long long)NO_, O_,
                                             nullptr, 0,
                                             HPS * M_, M_, 0,
                                             nullptr,
                                             partialS, HPS, N_, MTILES, ROWS_TOT,
                                             nullptr, 0, 0, 0,
                                             (long long)HPS * NM, (long long)HPS * MO,
                                             0.f);
    }
    {
        int n4 = (int)(NO_ / 4);
        reduce_out<<<(n4 + 255) / 256, 256>>>((const float4*)part6, bf,
                                              (float4*)out, n4);
    }
}

// round 16
// speedup vs baseline: 1.0414x; 1.0044x over previous
#include <cuda_runtime.h>
#include <cuda_fp16.h>
#include <cstdint>
#include <cstddef>

// ---------------------------------------------------------------------------
// MultiHeadMemory: H=16, M=1024, D=512, O=512, N=16384
// fp16 mma.sync engine at the legacy-HMMA roofline (~288 TF/s).
// R16: R15 config + fp16 split-K partials for GEMM6 (halves the serialized
// reduce tail traffic: 268 MB -> 134 MB).
//
// spine (s0): cvt mems, cvt Wk -> GEMM1(exp) -> [eK] GEMM4(exp, csFuse)
//             -> [e3b] GEMM6(rsFuse, split-K=4, fp16 partials) -> reduce(+bias)
// sB:  [fork] cvt Wv -> [eMems] GEMM2 -> [eWf] GEMM3b -> e3b
// sC:  [fork] cvt k -> eK ; cvt Wf -> eWf
// ---------------------------------------------------------------------------

#define H_  16
#define M_  1024
#define D_  512
#define O_  512
#define N_  16384

#define TBM 128
#define TBN 128
#define TBK 32          // halves per k-tile
#define ROWB 80         // bytes per SMEM row: 64 B data + 16 B pad
#define NSTG 3
#define STGB (2 * TBM * ROWB)            // A+B per stage = 20480 B
#define SCALEBUF 2048                    // smem bytes for fused scale buffers
#define SMEM_DYN (NSTG * STGB + SCALEBUF)    // 63488 B

#define MTILES   8                        // GEMM4 col tiles (M_/TBN)
#define ROWS_TOT (H_ * N_)                // 262144 softmax5 rows
#define MT3      4                        // GEMM1 col tiles (O_/TBN)
#define ROWS3    (H_ * M_)                // 16384 softmax3 rows
#define SPLIT6   4                        // GEMM6 head-group splits
#define HPS      (H_ / SPLIT6)            // 4 heads per split
#define NO_      ((size_t)N_ * O_)        // out elements

// fp16 scratch (static device globals; allocation-free kernel_launch)
__device__ __half g_kh[(size_t)N_ * O_];
__device__ __half g_memsh[(size_t)H_ * M_ * D_];
__device__ __half g_Wkh[(size_t)H_ * O_ * D_];
__device__ __half g_Wvh[(size_t)H_ * O_ * D_];
__device__ __half g_Wfh[(size_t)O_ * H_ * O_];
__device__ __half g_memkeyh[(size_t)H_ * M_ * O_];   // exp3 (unnormalized)
__device__ __half g_memvalh[(size_t)H_ * M_ * O_];
__device__ __half g_GTh[(size_t)H_ * M_ * O_];       // [h][O][M]
__device__ __half g_atth[(size_t)H_ * N_ * M_];      // exp5 (unnormalized)
__device__ float  g_partialS[(size_t)MTILES * ROWS_TOT]; // 8 MB
__device__ float  g_partialS3[(size_t)MT3 * ROWS3];      // 256 KB
__device__ __half g_part6[(size_t)SPLIT6 * NO_];         // 67 MB (fp16 partials)

// ---------------------------------------------------------------------------
__device__ __forceinline__ void cp_async16(uint32_t smem_addr, const void* gptr) {
    asm volatile("cp.async.cg.shared.global [%0], [%1], 16;\n"
                 :: "r"(smem_addr), "l"(gptr));
}
__device__ __forceinline__ void ldmatrix_x4(uint32_t& r0, uint32_t& r1,
                                            uint32_t& r2, uint32_t& r3,
                                            uint32_t addr) {
    asm volatile("ldmatrix.sync.aligned.m8n8.x4.shared.b16 {%0,%1,%2,%3}, [%4];"
                 : "=r"(r0), "=r"(r1), "=r"(r2), "=r"(r3) : "r"(addr));
}
__device__ __forceinline__ uint32_t mul_f16x2(uint32_t a, uint32_t b) {
    uint32_t r;
    asm("mul.f16x2 %0, %1, %2;" : "=r"(r) : "r"(a), "r"(b));
    return r;
}
__device__ __forceinline__ uint32_t h2bits(float lo, float hi) {
    __half2 h = __floats2half2_rn(lo, hi);
    return *reinterpret_cast<uint32_t*>(&h);
}

// ---------------------------------------------------------------------------
// fp32 -> fp16 convert (8 floats / thread)
// ---------------------------------------------------------------------------
__global__ void __launch_bounds__(256) cvt_f32_f16(
    const float4* __restrict__ in, uint2* __restrict__ out, int n8)
{
    int i = blockIdx.x * 256 + threadIdx.x;
    if (i < n8) {
        float4 a = in[2 * i];
        float4 b = in[2 * i + 1];
        uint2 o0, o1;
        o0.x = h2bits(a.x, a.y);
        o0.y = h2bits(a.z, a.w);
        o1.x = h2bits(b.x, b.y);
        o1.y = h2bits(b.z, b.w);
        out[2 * i] = o0;
        out[2 * i + 1] = o1;
    }
}

// ---------------------------------------------------------------------------
// out = p0 + p1 + p2 + p3 + bias. Partials fp16 (uint2 = 4 halves / thread).
// ---------------------------------------------------------------------------
__global__ void __launch_bounds__(256) reduce_out(
    const uint2* __restrict__ p, const float* __restrict__ bf,
    float4* __restrict__ out, int n4)
{
    int i = blockIdx.x * 256 + threadIdx.x;
    if (i < n4) {
        const size_t NO4 = NO_ / 4;   // uint2 stride per split
        float acc0 = 0.f, acc1 = 0.f, acc2 = 0.f, acc3 = 0.f;
#pragma unroll
        for (int s = 0; s < SPLIT6; ++s) {
            uint2 u = p[s * NO4 + i];
            float2 lo = __half22float2(*reinterpret_cast<__half2*>(&u.x));
            float2 hi = __half22float2(*reinterpret_cast<__half2*>(&u.y));
            acc0 += lo.x; acc1 += lo.y; acc2 += hi.x; acc3 += hi.y;
        }
        float4 bb = *reinterpret_cast<const float4*>(bf + (size_t)(i % (O_ / 4)) * 4);
        float4 o;
        o.x = acc0 + bb.x;
        o.y = acc1 + bb.y;
        o.z = acc2 + bb.z;
        o.w = acc3 + bb.w;
        out[i] = o;
    }
}

// ---------------------------------------------------------------------------
// fp16 tensor-core GEMM NT, fp32 accumulate:
//   C[m, n] = sum_k A[m, k] * B[n, k]  (+ bias[n])
// mode: 0 = fp32 out, 1 = fp16 out,
//       2 = fp16 exp(acc*colScale + bias - expShift) (fp32 __expf)
//           + deterministic row partial sums.
// kSplit>0: A/B indexed per head (aHead/bHead k-strides); blockIdx.z offsets
//           A/B by aZ/bZ (split-K by head groups).
// rsPart: fused row-scale — CTA recomputes 1/sum for rsHeads x TBM rows into
//         smem; A fragments scaled in-loop (fp16 mul).
// csPart: fused col-scale — CTA recomputes 1/sum for TBN cols into smem;
//         applied to accumulators in the mode-2 epilogue.
// ---------------------------------------------------------------------------
__global__ void __launch_bounds__(256, 2) gemm_nt_f16(
    const __half* __restrict__ A, long long aHead, long long lda,
    const __half* __restrict__ B, long long bHead, long long ldb,
    void* __restrict__ Cv, long long cHead, long long ldc,
    const float* __restrict__ bias, long long biasHead,
    int K, int kSplit, int mode,
    float* __restrict__ partialS,
    const float* __restrict__ rsPart, int rsHeads, long long rsLd,
    int rsTiles, long long rsStride,
    const float* __restrict__ csPart, long long csLd,
    int csTiles, long long csStride,
    long long aZ, long long bZ, float expShift)
{
    const int z = blockIdx.z;
    if (kSplit == 0) {
        A += (long long)z * aHead;
        B += (long long)z * bHead;
    } else {
        A += (long long)z * aZ;
        B += (long long)z * bZ;
    }
    if (bias) bias += (long long)z * biasHead;

    extern __shared__ __align__(16) char smraw[];
    const uint32_t smBase = (uint32_t)__cvta_generic_to_shared(smraw);
    const uint32_t BOFF = TBM * ROWB;
    float* scaleBuf = reinterpret_cast<float*>(smraw + NSTG * STGB);

    const int tid  = threadIdx.x;
    const int lane = tid & 31;
    const int warp = tid >> 5;
    const int g  = lane >> 2;
    const int tg = lane & 3;

    const int wm0 = (warp & 3) * 32;
    const int wn0 = (warp >> 2) * 64;

    const long long m0 = (long long)blockIdx.y * TBM;
    const long long n0 = (long long)blockIdx.x * TBN;

    // Fused scale recomputation (deterministic fixed-order sums).
    if (rsPart) {
        for (int idx = tid; idx < rsHeads * TBM; idx += 256) {
            const int hh = idx / TBM;
            const int rr = idx - hh * TBM;
            const long long base = ((long long)z * rsHeads + hh) * rsLd + m0 + rr;
            float s = 0.f;
            for (int t = 0; t < rsTiles; ++t) s += rsPart[(long long)t * rsStride + base];
            scaleBuf[idx] = 1.0f / s;
        }
    }
    if (csPart && tid < TBN) {
        const long long base = (long long)z * csLd + n0 + tid;
        float s = 0.f;
        for (int t = 0; t < csTiles; ++t) s += csPart[(long long)t * csStride + base];
        scaleBuf[tid] = 1.0f / s;
    }
    // published by the first mainloop __syncthreads (nIter >= 1 always here)

    const int pRow = tid >> 1;
    const int pCh  = (tid & 1) * 2;
    const uint32_t prodOff = (uint32_t)(pRow * ROWB + pCh * 16);

    const __half* aRowPtr = A + (m0 + pRow) * lda + pCh * 8;
    const __half* bRowPtr = B + (n0 + pRow) * ldb + pCh * 8;

    auto loadTile = [&](int kt, int stg) {
        const long long k0 = (long long)kt * TBK;
        long long kA, kB;
        if (kSplit > 0) {
            const long long kh = k0 / kSplit;
            const long long ko = k0 - kh * kSplit;
            kA = kh * aHead + ko;
            kB = kh * bHead + ko;
        } else {
            kA = k0; kB = k0;
        }
        const uint32_t ab = smBase + (uint32_t)stg * STGB + prodOff;
        const uint32_t bb = ab + BOFF;
#pragma unroll
        for (int c = 0; c < 2; ++c) {
            cp_async16(ab + c * 16, aRowPtr + kA + c * 8);
            cp_async16(bb + c * 16, bRowPtr + kB + c * 8);
        }
        asm volatile("cp.async.commit_group;\n" ::);
    };

    const int mat  = lane >> 3;
    const int row8 = lane & 7;
    uint32_t aOff[2], bOff[4];
#pragma unroll
    for (int i = 0; i < 2; ++i)
        aOff[i] = (uint32_t)((wm0 + i * 16 + (mat & 1) * 8 + row8) * ROWB
                             + (mat >> 1) * 16);
#pragma unroll
    for (int p = 0; p < 4; ++p)
        bOff[p] = (uint32_t)(BOFF + (wn0 + (2 * p + (mat >> 1)) * 8 + row8) * ROWB
                             + (mat & 1) * 16);

    float acc[2][8][4];
#pragma unroll
    for (int i = 0; i < 2; ++i)
#pragma unroll
        for (int j = 0; j < 8; ++j)
#pragma unroll
            for (int r = 0; r < 4; ++r) acc[i][j][r] = 0.f;

    uint32_t sreg[2][2];
    int lastKh = -1;

    const int nIter = K / TBK;
    loadTile(0, 0);
    if (nIter > 1) loadTile(1, 1);

    int stg = 0;
    for (int kt = 0; kt < nIter; ++kt) {
        if (kt + 1 < nIter) {
            asm volatile("cp.async.wait_group 1;\n" ::);
        } else {
            asm volatile("cp.async.wait_group 0;\n" ::);
        }
        __syncthreads();

        if (kt + 2 < nIter) {
            int ns = stg + 2; if (ns >= NSTG) ns -= NSTG;
            loadTile(kt + 2, ns);
        }

        if (rsPart) {
            const int kh = (int)(((long long)kt * TBK) / kSplit);
            if (kh != lastKh) {
                lastKh = kh;
#pragma unroll
                for (int i = 0; i < 2; ++i) {
                    const int lr = wm0 + i * 16 + g;
                    float s0 = scaleBuf[kh * TBM + lr];
                    float s1 = scaleBuf[kh * TBM + lr + 8];
                    sreg[i][0] = h2bits(s0, s0);
                    sreg[i][1] = h2bits(s1, s1);
                }
            }
        }

        const uint32_t base = smBase + (uint32_t)stg * STGB;
#pragma unroll
        for (int ks = 0; ks < 2; ++ks) {
            const uint32_t ksb = base + ks * 32;
            uint32_t af[2][4];
#pragma unroll
            for (int i = 0; i < 2; ++i)
                ldmatrix_x4(af[i][0], af[i][1], af[i][2], af[i][3], ksb + aOff[i]);
            if (rsPart) {
#pragma unroll
                for (int i = 0; i < 2; ++i) {
                    af[i][0] = mul_f16x2(af[i][0], sreg[i][0]);
                    af[i][1] = mul_f16x2(af[i][1], sreg[i][1]);
                    af[i][2] = mul_f16x2(af[i][2], sreg[i][0]);
                    af[i][3] = mul_f16x2(af[i][3], sreg[i][1]);
                }
            }
            uint32_t bf[8][2];
#pragma unroll
            for (int p = 0; p < 4; ++p)
                ldmatrix_x4(bf[2 * p][0], bf[2 * p][1],
                            bf[2 * p + 1][0], bf[2 * p + 1][1], ksb + bOff[p]);
#pragma unroll
            for (int i = 0; i < 2; ++i) {
#pragma unroll
                for (int j = 0; j < 8; ++j) {
                    asm volatile(
                        "mma.sync.aligned.m16n8k16.row.col.f32.f16.f16.f32 "
                        "{%0,%1,%2,%3}, {%4,%5,%6,%7}, {%8,%9}, {%0,%1,%2,%3};"
                        : "+f"(acc[i][j][0]), "+f"(acc[i][j][1]),
                          "+f"(acc[i][j][2]), "+f"(acc[i][j][3])
                        : "r"(af[i][0]), "r"(af[i][1]), "r"(af[i][2]), "r"(af[i][3]),
                          "r"(bf[j][0]), "r"(bf[j][1]));
                }
            }
        }
        ++stg; if (stg == NSTG) stg = 0;
    }

    const long long cBase = (long long)z * cHead;

    if (mode == 2) {
        __half* C = (__half*)Cv + cBase;
        float rsum[2][2] = {{0.f, 0.f}, {0.f, 0.f}};
#pragma unroll
        for (int i = 0; i < 2; ++i) {
            const long long r0 = m0 + wm0 + i * 16 + g;
#pragma unroll
            for (int j = 0; j < 8; ++j) {
                const int ccl = wn0 + j * 8 + 2 * tg;
                const long long cc = n0 + ccl;
                float a00 = acc[i][j][0], a01 = acc[i][j][1];
                float a10 = acc[i][j][2], a11 = acc[i][j][3];
                if (csPart) {
                    float s0 = scaleBuf[ccl], s1 = scaleBuf[ccl + 1];
                    a00 *= s0; a01 *= s1; a10 *= s0; a11 *= s1;
                }
                if (bias) {
                    float b0 = bias[cc], b1 = bias[cc + 1];
                    a00 += b0; a01 += b1; a10 += b0; a11 += b1;
                }
                float e00 = __expf(a00 - expShift);
                float e01 = __expf(a01 - expShift);
                float e10 = __expf(a10 - expShift);
                float e11 = __expf(a11 - expShift);
                rsum[i][0] += e00 + e01;
                rsum[i][1] += e10 + e11;
                *reinterpret_cast<uint32_t*>(C + r0 * ldc + cc) = h2bits(e00, e01);
                *reinterpret_cast<uint32_t*>(C + (r0 + 8) * ldc + cc) = h2bits(e10, e11);
            }
        }
#pragma unroll
        for (int i = 0; i < 2; ++i) {
#pragma unroll
            for (int hh = 0; hh < 2; ++hh) {
                rsum[i][hh] += __shfl_xor_sync(0xffffffffu, rsum[i][hh], 1);
                rsum[i][hh] += __shfl_xor_sync(0xffffffffu, rsum[i][hh], 2);
            }
        }
        float* sbuf = reinterpret_cast<float*>(smraw);
        __syncthreads();
        if (tg == 0) {
#pragma unroll
            for (int i = 0; i < 2; ++i) {
                sbuf[warp * 32 + 16 * i + g]     = rsum[i][0];
                sbuf[warp * 32 + 16 * i + g + 8] = rsum[i][1];
            }
        }
        __syncthreads();
        if (tid < TBM) {
            const int wq = tid >> 5;
            const int lr = tid & 31;
            const float s = sbuf[wq * 32 + lr] + sbuf[(wq + 4) * 32 + lr];
            const long long rows = (long long)gridDim.y * TBM;
            partialS[((long long)blockIdx.x * gridDim.z + z) * rows + m0 + tid] = s;
        }
        return;
    }

#pragma unroll
    for (int i = 0; i < 2; ++i) {
        const long long r0 = m0 + wm0 + i * 16 + g;
#pragma unroll
        for (int j = 0; j < 8; ++j) {
            const long long cc = n0 + wn0 + j * 8 + 2 * tg;
            float b0 = 0.f, b1 = 0.f;
            if (bias) { b0 = bias[cc]; b1 = bias[cc + 1]; }
            float v00 = acc[i][j][0] + b0, v01 = acc[i][j][1] + b1;
            float v10 = acc[i][j][2] + b0, v11 = acc[i][j][3] + b1;
            if (mode == 1) {
                __half* C = (__half*)Cv + cBase;
                *reinterpret_cast<uint32_t*>(C + r0 * ldc + cc) = h2bits(v00, v01);
                *reinterpret_cast<uint32_t*>(C + (r0 + 8) * ldc + cc) = h2bits(v10, v11);
            } else {
                float* C = (float*)Cv + cBase;
                *reinterpret_cast<float2*>(C + r0 * ldc + cc) = make_float2(v00, v01);
                *reinterpret_cast<float2*>(C + (r0 + 8) * ldc + cc) = make_float2(v10, v11);
            }
        }
    }
}

// ---------------------------------------------------------------------------
// Launch
// ---------------------------------------------------------------------------
extern "C" void kernel_launch(void* const* d_in, const int* in_sizes, int n_in,
                              void* d_out, int out_size)
{
    const float* k_in = (const float*)d_in[0];   // [N, O]
    const float* mems = (const float*)d_in[1];   // [H, M, D]
    const float* Wk   = (const float*)d_in[2];   // [H, O, D]
    const float* bk   = (const float*)d_in[3];   // [H, O]
    const float* Wv   = (const float*)d_in[4];   // [H, O, D]
    const float* bv   = (const float*)d_in[5];   // [H, O]
    const float* Wf   = (const float*)d_in[6];   // [O, H*O]
    const float* bf   = (const float*)d_in[7];   // [O]
    float* out = (float*)d_out;                  // [N, O]

    cudaFuncSetAttribute(gemm_nt_f16,
                         cudaFuncAttributeMaxDynamicSharedMemorySize, SMEM_DYN);

    static cudaStream_t sB = nullptr, sC = nullptr;
    static cudaEvent_t eFork, eMems, eK, eWf, e3b;
    if (sB == nullptr) {
        cudaStreamCreateWithFlags(&sB, cudaStreamNonBlocking);
        cudaStreamCreateWithFlags(&sC, cudaStreamNonBlocking);
        cudaEventCreateWithFlags(&eFork, cudaEventDisableTiming);
        cudaEventCreateWithFlags(&eMems, cudaEventDisableTiming);
        cudaEventCreateWithFlags(&eK,    cudaEventDisableTiming);
        cudaEventCreateWithFlags(&eWf,   cudaEventDisableTiming);
        cudaEventCreateWithFlags(&e3b,   cudaEventDisableTiming);
    }

    __half *kh, *memsh, *Wkh, *Wvh, *Wfh, *memkeyh, *memvalh, *GTh, *atth, *part6;
    float *partialS, *partialS3;
    cudaGetSymbolAddress((void**)&kh,        g_kh);
    cudaGetSymbolAddress((void**)&memsh,     g_memsh);
    cudaGetSymbolAddress((void**)&Wkh,       g_Wkh);
    cudaGetSymbolAddress((void**)&Wvh,       g_Wvh);
    cudaGetSymbolAddress((void**)&Wfh,       g_Wfh);
    cudaGetSymbolAddress((void**)&memkeyh,   g_memkeyh);
    cudaGetSymbolAddress((void**)&memvalh,   g_memvalh);
    cudaGetSymbolAddress((void**)&GTh,       g_GTh);
    cudaGetSymbolAddress((void**)&atth,      g_atth);
    cudaGetSymbolAddress((void**)&partialS,  g_partialS);
    cudaGetSymbolAddress((void**)&partialS3, g_partialS3);
    cudaGetSymbolAddress((void**)&part6,     g_part6);

    const long long MD = (long long)M_ * D_;
    const long long OD = (long long)O_ * D_;
    const long long MO = (long long)M_ * O_;
    const long long NM = (long long)N_ * M_;

    auto cvtOn = [&](cudaStream_t s, const float* src, __half* dst, long long n) {
        int n8 = (int)(n / 8);
        cvt_f32_f16<<<(n8 + 255) / 256, 256, 0, s>>>(
            (const float4*)src, (uint2*)dst, n8);
    };

    // ---- fork ----
    cudaEventRecord(eFork, 0);
    cudaStreamWaitEvent(sB, eFork, 0);
    cudaStreamWaitEvent(sC, eFork, 0);

    // sC: cvt k, cvt Wf
    cvtOn(sC, k_in, kh, (long long)N_ * O_);
    cudaEventRecord(eK, sC);
    cvtOn(sC, Wf, Wfh, (long long)O_ * H_ * O_);
    cudaEventRecord(eWf, sC);

    // spine: cvt mems, cvt Wk
    cvtOn(0, mems, memsh, (long long)H_ * M_ * D_);
    cudaEventRecord(eMems, 0);
    cvtOn(0, Wk, Wkh, (long long)H_ * O_ * D_);

    // sB: cvt Wv -> GEMM2 -> GEMM3b
    cvtOn(sB, Wv, Wvh, (long long)H_ * O_ * D_);
    cudaStreamWaitEvent(sB, eMems, 0);
    {
        dim3 grid(O_ / TBN, M_ / TBM, H_);
        gemm_nt_f16<<<grid, 256, SMEM_DYN, sB>>>(memsh, MD, D_, Wvh, OD, D_,
                                                 memvalh, MO, O_, bv, O_, D_, 0, 1,
                                                 nullptr,
                                                 nullptr, 0, 0, 0, 0,
                                                 nullptr, 0, 0, 0,
                                                 0, 0, 0.f);
    }
    cudaStreamWaitEvent(sB, eWf, 0);
    {
        dim3 grid(M_ / TBN, O_ / TBM, H_);
        gemm_nt_f16<<<grid, 256, SMEM_DYN, sB>>>(Wfh, O_, (long long)H_ * O_,
                                                 memvalh, MO, O_,
                                                 GTh, MO, M_, nullptr, 0, O_, 0, 1,
                                                 nullptr,
                                                 nullptr, 0, 0, 0, 0,
                                                 nullptr, 0, 0, 0,
                                                 0, 0, 0.f);
    }
    cudaEventRecord(e3b, sB);

    // spine: GEMM1 exp mode (exp(logit + bk), row partial sums)
    {
        dim3 grid(O_ / TBN, M_ / TBM, H_);
        gemm_nt_f16<<<grid, 256, SMEM_DYN>>>(memsh, MD, D_, Wkh, OD, D_,
                                             memkeyh, MO, O_, bk, O_, D_, 0, 2,
                                             partialS3,
                                             nullptr, 0, 0, 0, 0,
                                             nullptr, 0, 0, 0,
                                             0, 0, 0.0f);
    }

    // spine: GEMM4 exp mode, col-scale fused from partialS3 (invS3 recompute)
    cudaStreamWaitEvent(0, eK, 0);
    {
        dim3 grid(M_ / TBN, N_ / TBM, H_);
        gemm_nt_f16<<<grid, 256, SMEM_DYN>>>(kh, 0, O_, memkeyh, MO, O_,
                                             atth, NM, M_, nullptr, 0, O_, 0, 2,
                                             partialS,
                                             nullptr, 0, 0, 0, 0,
                                             partialS3, M_, MT3, ROWS3,
                                             0, 0, 4.0f);
    }

    // join: GEMM6 split-K=4 by head group, row-scale fused, fp16 partials
    cudaStreamWaitEvent(0, e3b, 0);
    {
        dim3 grid(O_ / TBN, N_ / TBM, SPLIT6);
        gemm_nt_f16<<<grid, 256, SMEM_DYN>>>(atth, NM, M_, GTh, MO, M_,
                                             part6, (long long)NO_, O_,
                                             nullptr, 0,
                                             HPS * M_, M_, 1,
                                             nullptr,
                                             partialS, HPS, N_, MTILES, ROWS_TOT,
                                             nullptr, 0, 0, 0,
                                             (long long)HPS * NM, (long long)HPS * MO,
                                             0.f);
    }
    {
        int n4 = (int)(NO_ / 4);
        reduce_out<<<(n4 + 255) / 256, 256>>>((const uint2*)part6, bf,
                                              (float4*)out, n4);
    }
}

// round 17
// speedup vs baseline: 1.1254x; 1.0807x over previous
#include <cuda_runtime.h>
#include <cuda_fp16.h>
#include <cstdint>
#include <cstddef>

// ---------------------------------------------------------------------------
// MultiHeadMemory: H=16, M=1024, D=512, O=512, N=16384
// fp16 mma.sync engine at the legacy-HMMA roofline (~288 TF/s).
// R17: R16 config + (a) cvt Wk moved to sC head so GEMM1 starts ~7us earlier;
// (b) 64-bit divisions in loadTile / row-scale kh replaced with incremental
// counters (loadTile calls are strictly sequential in kt).
//
// spine (s0): cvt mems -> [eWk] GEMM1(exp) -> [eK] GEMM4(exp, csFuse)
//             -> [e3b] GEMM6(rsFuse, split-K=4, fp16 partials) -> reduce(+bias)
// sB:  [fork] cvt Wv -> [eMems] GEMM2 -> [eWf] GEMM3b -> e3b
// sC:  [fork] cvt Wk -> eWk ; cvt k -> eK ; cvt Wf -> eWf
// ---------------------------------------------------------------------------

#define H_  16
#define M_  1024
#define D_  512
#define O_  512
#define N_  16384

#define TBM 128
#define TBN 128
#define TBK 32          // halves per k-tile
#define ROWB 80         // bytes per SMEM row: 64 B data + 16 B pad
#define NSTG 3
#define STGB (2 * TBM * ROWB)            // A+B per stage = 20480 B
#define SCALEBUF 2048                    // smem bytes for fused scale buffers
#define SMEM_DYN (NSTG * STGB + SCALEBUF)    // 63488 B

#define MTILES   8                        // GEMM4 col tiles (M_/TBN)
#define ROWS_TOT (H_ * N_)                // 262144 softmax5 rows
#define MT3      4                        // GEMM1 col tiles (O_/TBN)
#define ROWS3    (H_ * M_)                // 16384 softmax3 rows
#define SPLIT6   4                        // GEMM6 head-group splits
#define HPS      (H_ / SPLIT6)            // 4 heads per split
#define NO_      ((size_t)N_ * O_)        // out elements

// fp16 scratch (static device globals; allocation-free kernel_launch)
__device__ __half g_kh[(size_t)N_ * O_];
__device__ __half g_memsh[(size_t)H_ * M_ * D_];
__device__ __half g_Wkh[(size_t)H_ * O_ * D_];
__device__ __half g_Wvh[(size_t)H_ * O_ * D_];
__device__ __half g_Wfh[(size_t)O_ * H_ * O_];
__device__ __half g_memkeyh[(size_t)H_ * M_ * O_];   // exp3 (unnormalized)
__device__ __half g_memvalh[(size_t)H_ * M_ * O_];
__device__ __half g_GTh[(size_t)H_ * M_ * O_];       // [h][O][M]
__device__ __half g_atth[(size_t)H_ * N_ * M_];      // exp5 (unnormalized)
__device__ float  g_partialS[(size_t)MTILES * ROWS_TOT]; // 8 MB
__device__ float  g_partialS3[(size_t)MT3 * ROWS3];      // 256 KB
__device__ __half g_part6[(size_t)SPLIT6 * NO_];         // 67 MB (fp16 partials)

// ---------------------------------------------------------------------------
__device__ __forceinline__ void cp_async16(uint32_t smem_addr, const void* gptr) {
    asm volatile("cp.async.cg.shared.global [%0], [%1], 16;\n"
                 :: "r"(smem_addr), "l"(gptr));
}
__device__ __forceinline__ void ldmatrix_x4(uint32_t& r0, uint32_t& r1,
                                            uint32_t& r2, uint32_t& r3,
                                            uint32_t addr) {
    asm volatile("ldmatrix.sync.aligned.m8n8.x4.shared.b16 {%0,%1,%2,%3}, [%4];"
                 : "=r"(r0), "=r"(r1), "=r"(r2), "=r"(r3) : "r"(addr));
}
__device__ __forceinline__ uint32_t mul_f16x2(uint32_t a, uint32_t b) {
    uint32_t r;
    asm("mul.f16x2 %0, %1, %2;" : "=r"(r) : "r"(a), "r"(b));
    return r;
}
__device__ __forceinline__ uint32_t h2bits(float lo, float hi) {
    __half2 h = __floats2half2_rn(lo, hi);
    return *reinterpret_cast<uint32_t*>(&h);
}

// ---------------------------------------------------------------------------
// fp32 -> fp16 convert (8 floats / thread)
// ---------------------------------------------------------------------------
__global__ void __launch_bounds__(256) cvt_f32_f16(
    const float4* __restrict__ in, uint2* __restrict__ out, int n8)
{
    int i = blockIdx.x * 256 + threadIdx.x;
    if (i < n8) {
        float4 a = in[2 * i];
        float4 b = in[2 * i + 1];
        uint2 o0, o1;
        o0.x = h2bits(a.x, a.y);
        o0.y = h2bits(a.z, a.w);
        o1.x = h2bits(b.x, b.y);
        o1.y = h2bits(b.z, b.w);
        out[2 * i] = o0;
        out[2 * i + 1] = o1;
    }
}

// ---------------------------------------------------------------------------
// out = p0 + p1 + p2 + p3 + bias. Partials fp16 (uint2 = 4 halves / thread).
// ---------------------------------------------------------------------------
__global__ void __launch_bounds__(256) reduce_out(
    const uint2* __restrict__ p, const float* __restrict__ bf,
    float4* __restrict__ out, int n4)
{
    int i = blockIdx.x * 256 + threadIdx.x;
    if (i < n4) {
        const size_t NO4 = NO_ / 4;   // uint2 stride per split
        float acc0 = 0.f, acc1 = 0.f, acc2 = 0.f, acc3 = 0.f;
#pragma unroll
        for (int s = 0; s < SPLIT6; ++s) {
            uint2 u = p[s * NO4 + i];
            float2 lo = __half22float2(*reinterpret_cast<__half2*>(&u.x));
            float2 hi = __half22float2(*reinterpret_cast<__half2*>(&u.y));
            acc0 += lo.x; acc1 += lo.y; acc2 += hi.x; acc3 += hi.y;
        }
        float4 bb = *reinterpret_cast<const float4*>(bf + (size_t)(i % (O_ / 4)) * 4);
        float4 o;
        o.x = acc0 + bb.x;
        o.y = acc1 + bb.y;
        o.z = acc2 + bb.z;
        o.w = acc3 + bb.w;
        out[i] = o;
    }
}

// ---------------------------------------------------------------------------
// fp16 tensor-core GEMM NT, fp32 accumulate:
//   C[m, n] = sum_k A[m, k] * B[n, k]  (+ bias[n])
// mode: 0 = fp32 out, 1 = fp16 out,
//       2 = fp16 exp(acc*colScale + bias - expShift) (fp32 __expf)
//           + deterministic row partial sums.
// kSplit>0: A/B indexed per head (aHead/bHead k-strides); blockIdx.z offsets
//           A/B by aZ/bZ (split-K by head groups). Head boundaries tracked
//           incrementally (no divisions in the mainloop).
// rsPart: fused row-scale — CTA recomputes 1/sum for rsHeads x TBM rows into
//         smem; A fragments scaled in-loop (fp16 mul).
// csPart: fused col-scale — CTA recomputes 1/sum for TBN cols into smem;
//         applied to accumulators in the mode-2 epilogue.
// ---------------------------------------------------------------------------
__global__ void __launch_bounds__(256, 2) gemm_nt_f16(
    const __half* __restrict__ A, long long aHead, long long lda,
    const __half* __restrict__ B, long long bHead, long long ldb,
    void* __restrict__ Cv, long long cHead, long long ldc,
    const float* __restrict__ bias, long long biasHead,
    int K, int kSplit, int mode,
    float* __restrict__ partialS,
    const float* __restrict__ rsPart, int rsHeads, long long rsLd,
    int rsTiles, long long rsStride,
    const float* __restrict__ csPart, long long csLd,
    int csTiles, long long csStride,
    long long aZ, long long bZ, float expShift)
{
    const int z = blockIdx.z;
    if (kSplit == 0) {
        A += (long long)z * aHead;
        B += (long long)z * bHead;
    } else {
        A += (long long)z * aZ;
        B += (long long)z * bZ;
    }
    if (bias) bias += (long long)z * biasHead;

    extern __shared__ __align__(16) char smraw[];
    const uint32_t smBase = (uint32_t)__cvta_generic_to_shared(smraw);
    const uint32_t BOFF = TBM * ROWB;
    float* scaleBuf = reinterpret_cast<float*>(smraw + NSTG * STGB);

    const int tid  = threadIdx.x;
    const int lane = tid & 31;
    const int warp = tid >> 5;
    const int g  = lane >> 2;
    const int tg = lane & 3;

    const int wm0 = (warp & 3) * 32;
    const int wn0 = (warp >> 2) * 64;

    const long long m0 = (long long)blockIdx.y * TBM;
    const long long n0 = (long long)blockIdx.x * TBN;

    // Fused scale recomputation (deterministic fixed-order sums).
    if (rsPart) {
        for (int idx = tid; idx < rsHeads * TBM; idx += 256) {
            const int hh = idx / TBM;
            const int rr = idx - hh * TBM;
            const long long base = ((long long)z * rsHeads + hh) * rsLd + m0 + rr;
            float s = 0.f;
            for (int t = 0; t < rsTiles; ++t) s += rsPart[(long long)t * rsStride + base];
            scaleBuf[idx] = 1.0f / s;
        }
    }
    if (csPart && tid < TBN) {
        const long long base = (long long)z * csLd + n0 + tid;
        float s = 0.f;
        for (int t = 0; t < csTiles; ++t) s += csPart[(long long)t * csStride + base];
        scaleBuf[tid] = 1.0f / s;
    }
    // published by the first mainloop __syncthreads (nIter >= 1 always here)

    const int pRow = tid >> 1;
    const int pCh  = (tid & 1) * 2;
    const uint32_t prodOff = (uint32_t)(pRow * ROWB + pCh * 16);

    const __half* aRowPtr = A + (m0 + pRow) * lda + pCh * 8;
    const __half* bRowPtr = B + (n0 + pRow) * ldb + pCh * 8;

    // Incremental k-offset tracking (loadTile is called with kt strictly
    // ascending: 0, 1, 2, ...). perHead = k-tiles per head when kSplit>0.
    const int perHead = (kSplit > 0) ? (kSplit / TBK) : 0x7fffffff;
    long long kAcur = 0, kBcur = 0;
    int loadTick = 0;

    auto loadTile = [&](int stg) {
        const uint32_t ab = smBase + (uint32_t)stg * STGB + prodOff;
        const uint32_t bb = ab + BOFF;
#pragma unroll
        for (int c = 0; c < 2; ++c) {
            cp_async16(ab + c * 16, aRowPtr + kAcur + c * 8);
            cp_async16(bb + c * 16, bRowPtr + kBcur + c * 8);
        }
        asm volatile("cp.async.commit_group;\n" ::);
        // advance
        if (++loadTick == perHead) {
            loadTick = 0;
            kAcur += aHead - (long long)(kSplit - TBK);
            kBcur += bHead - (long long)(kSplit - TBK);
        } else {
            kAcur += TBK;
            kBcur += TBK;
        }
    };

    const int mat  = lane >> 3;
    const int row8 = lane & 7;
    uint32_t aOff[2], bOff[4];
#pragma unroll
    for (int i = 0; i < 2; ++i)
        aOff[i] = (uint32_t)((wm0 + i * 16 + (mat & 1) * 8 + row8) * ROWB
                             + (mat >> 1) * 16);
#pragma unroll
    for (int p = 0; p < 4; ++p)
        bOff[p] = (uint32_t)(BOFF + (wn0 + (2 * p + (mat >> 1)) * 8 + row8) * ROWB
                             + (mat & 1) * 16);

    float acc[2][8][4];
#pragma unroll
    for (int i = 0; i < 2; ++i)
#pragma unroll
        for (int j = 0; j < 8; ++j)
#pragma unroll
            for (int r = 0; r < 4; ++r) acc[i][j][r] = 0.f;

    uint32_t sreg[2][2];
    int rsTick = 0;     // k-tiles remaining in current head (0 -> reload)
    int rsKh   = 0;     // current head index for row scales

    const int nIter = K / TBK;
    loadTile(0);
    if (nIter > 1) loadTile(1);

    int stg = 0;
    for (int kt = 0; kt < nIter; ++kt) {
        if (kt + 1 < nIter) {
            asm volatile("cp.async.wait_group 1;\n" ::);
        } else {
            asm volatile("cp.async.wait_group 0;\n" ::);
        }
        __syncthreads();

        if (kt + 2 < nIter) {
            int ns = stg + 2; if (ns >= NSTG) ns -= NSTG;
            loadTile(ns);
        }

        if (rsPart) {
            if (rsTick == 0) {
#pragma unroll
                for (int i = 0; i < 2; ++i) {
                    const int lr = wm0 + i * 16 + g;
                    float s0 = scaleBuf[rsKh * TBM + lr];
                    float s1 = scaleBuf[rsKh * TBM + lr + 8];
                    sreg[i][0] = h2bits(s0, s0);
                    sreg[i][1] = h2bits(s1, s1);
                }
            }
            if (++rsTick == perHead) { rsTick = 0; ++rsKh; }
        }

        const uint32_t base = smBase + (uint32_t)stg * STGB;
#pragma unroll
        for (int ks = 0; ks < 2; ++ks) {
            const uint32_t ksb = base + ks * 32;
            uint32_t af[2][4];
#pragma unroll
            for (int i = 0; i < 2; ++i)
                ldmatrix_x4(af[i][0], af[i][1], af[i][2], af[i][3], ksb + aOff[i]);
            if (rsPart) {
#pragma unroll
                for (int i = 0; i < 2; ++i) {
                    af[i][0] = mul_f16x2(af[i][0], sreg[i][0]);
                    af[i][1] = mul_f16x2(af[i][1], sreg[i][1]);
                    af[i][2] = mul_f16x2(af[i][2], sreg[i][0]);
                    af[i][3] = mul_f16x2(af[i][3], sreg[i][1]);
                }
            }
            uint32_t bf[8][2];
#pragma unroll
            for (int p = 0; p < 4; ++p)
                ldmatrix_x4(bf[2 * p][0], bf[2 * p][1],
                            bf[2 * p + 1][0], bf[2 * p + 1][1], ksb + bOff[p]);
#pragma unroll
            for (int i = 0; i < 2; ++i) {
#pragma unroll
                for (int j = 0; j < 8; ++j) {
                    asm volatile(
                        "mma.sync.aligned.m16n8k16.row.col.f32.f16.f16.f32 "
                        "{%0,%1,%2,%3}, {%4,%5,%6,%7}, {%8,%9}, {%0,%1,%2,%3};"
                        : "+f"(acc[i][j][0]), "+f"(acc[i][j][1]),
                          "+f"(acc[i][j][2]), "+f"(acc[i][j][3])
                        : "r"(af[i][0]), "r"(af[i][1]), "r"(af[i][2]), "r"(af[i][3]),
                          "r"(bf[j][0]), "r"(bf[j][1]));
                }
            }
        }
        ++stg; if (stg == NSTG) stg = 0;
    }

    const long long cBase = (long long)z * cHead;

    if (mode == 2) {
        __half* C = (__half*)Cv + cBase;
        float rsum[2][2] = {{0.f, 0.f}, {0.f, 0.f}};
#pragma unroll
        for (int i = 0; i < 2; ++i) {
            const long long r0 = m0 + wm0 + i * 16 + g;
#pragma unroll
            for (int j = 0; j < 8; ++j) {
                const int ccl = wn0 + j * 8 + 2 * tg;
                const long long cc = n0 + ccl;
                float a00 = acc[i][j][0], a01 = acc[i][j][1];
                float a10 = acc[i][j][2], a11 = acc[i][j][3];
                if (csPart) {
                    float s0 = scaleBuf[ccl], s1 = scaleBuf[ccl + 1];
                    a00 *= s0; a01 *= s1; a10 *= s0; a11 *= s1;
                }
                if (bias) {
                    float b0 = bias[cc], b1 = bias[cc + 1];
                    a00 += b0; a01 += b1; a10 += b0; a11 += b1;
                }
                float e00 = __expf(a00 - expShift);
                float e01 = __expf(a01 - expShift);
                float e10 = __expf(a10 - expShift);
                float e11 = __expf(a11 - expShift);
                rsum[i][0] += e00 + e01;
                rsum[i][1] += e10 + e11;
                *reinterpret_cast<uint32_t*>(C + r0 * ldc + cc) = h2bits(e00, e01);
                *reinterpret_cast<uint32_t*>(C + (r0 + 8) * ldc + cc) = h2bits(e10, e11);
            }
        }
#pragma unroll
        for (int i = 0; i < 2; ++i) {
#pragma unroll
            for (int hh = 0; hh < 2; ++hh) {
                rsum[i][hh] += __shfl_xor_sync(0xffffffffu, rsum[i][hh], 1);
                rsum[i][hh] += __shfl_xor_sync(0xffffffffu, rsum[i][hh], 2);
            }
        }
        float* sbuf = reinterpret_cast<float*>(smraw);
        __syncthreads();
        if (tg == 0) {
#pragma unroll
            for (int i = 0; i < 2; ++i) {
                sbuf[warp * 32 + 16 * i + g]     = rsum[i][0];
                sbuf[warp * 32 + 16 * i + g + 8] = rsum[i][1];
            }
        }
        __syncthreads();
        if (tid < TBM) {
            const int wq = tid >> 5;
            const int lr = tid & 31;
            const float s = sbuf[wq * 32 + lr] + sbuf[(wq + 4) * 32 + lr];
            const long long rows = (long long)gridDim.y * TBM;
            partialS[((long long)blockIdx.x * gridDim.z + z) * rows + m0 + tid] = s;
        }
        return;
    }

#pragma unroll
    for (int i = 0; i < 2; ++i) {
        const long long r0 = m0 + wm0 + i * 16 + g;
#pragma unroll
        for (int j = 0; j < 8; ++j) {
            const long long cc = n0 + wn0 + j * 8 + 2 * tg;
            float b0 = 0.f, b1 = 0.f;
            if (bias) { b0 = bias[cc]; b1 = bias[cc + 1]; }
            float v00 = acc[i][j][0] + b0, v01 = acc[i][j][1] + b1;
            float v10 = acc[i][j][2] + b0, v11 = acc[i][j][3] + b1;
            if (mode == 1) {
                __half* C = (__half*)Cv + cBase;
                *reinterpret_cast<uint32_t*>(C + r0 * ldc + cc) = h2bits(v00, v01);
                *reinterpret_cast<uint32_t*>(C + (r0 + 8) * ldc + cc) = h2bits(v10, v11);
            } else {
                float* C = (float*)Cv + cBase;
                *reinterpret_cast<float2*>(C + r0 * ldc + cc) = make_float2(v00, v01);
                *reinterpret_cast<float2*>(C + (r0 + 8) * ldc + cc) = make_float2(v10, v11);
            }
        }
    }
}

// ---------------------------------------------------------------------------
// Launch
// ---------------------------------------------------------------------------
extern "C" void kernel_launch(void* const* d_in, const int* in_sizes, int n_in,
                              void* d_out, int out_size)
{
    const float* k_in = (const float*)d_in[0];   // [N, O]
    const float* mems = (const float*)d_in[1];   // [H, M, D]
    const float* Wk   = (const float*)d_in[2];   // [H, O, D]
    const float* bk   = (const float*)d_in[3];   // [H, O]
    const float* Wv   = (const float*)d_in[4];   // [H, O, D]
    const float* bv   = (const float*)d_in[5];   // [H, O]
    const float* Wf   = (const float*)d_in[6];   // [O, H*O]
    const float* bf   = (const float*)d_in[7];   // [O]
    float* out = (float*)d_out;                  // [N, O]

    cudaFuncSetAttribute(gemm_nt_f16,
                         cudaFuncAttributeMaxDynamicSharedMemorySize, SMEM_DYN);

    static cudaStream_t sB = nullptr, sC = nullptr;
    static cudaEvent_t eFork, eMems, eWk, eK, eWf, e3b;
    if (sB == nullptr) {
        cudaStreamCreateWithFlags(&sB, cudaStreamNonBlocking);
        cudaStreamCreateWithFlags(&sC, cudaStreamNonBlocking);
        cudaEventCreateWithFlags(&eFork, cudaEventDisableTiming);
        cudaEventCreateWithFlags(&eMems, cudaEventDisableTiming);
        cudaEventCreateWithFlags(&eWk,   cudaEventDisableTiming);
        cudaEventCreateWithFlags(&eK,    cudaEventDisableTiming);
        cudaEventCreateWithFlags(&eWf,   cudaEventDisableTiming);
        cudaEventCreateWithFlags(&e3b,   cudaEventDisableTiming);
    }

    __half *kh, *memsh, *Wkh, *Wvh, *Wfh, *memkeyh, *memvalh, *GTh, *atth, *part6;
    float *partialS, *partialS3;
    cudaGetSymbolAddress((void**)&kh,        g_kh);
    cudaGetSymbolAddress((void**)&memsh,     g_memsh);
    cudaGetSymbolAddress((void**)&Wkh,       g_Wkh);
    cudaGetSymbolAddress((void**)&Wvh,       g_Wvh);
    cudaGetSymbolAddress((void**)&Wfh,       g_Wfh);
    cudaGetSymbolAddress((void**)&memkeyh,   g_memkeyh);
    cudaGetSymbolAddress((void**)&memvalh,   g_memvalh);
    cudaGetSymbolAddress((void**)&GTh,       g_GTh);
    cudaGetSymbolAddress((void**)&atth,      g_atth);
    cudaGetSymbolAddress((void**)&partialS,  g_partialS);
    cudaGetSymbolAddress((void**)&partialS3, g_partialS3);
    cudaGetSymbolAddress((void**)&part6,     g_part6);

    const long long MD = (long long)M_ * D_;
    const long long OD = (long long)O_ * D_;
    const long long MO = (long long)M_ * O_;
    const long long NM = (long long)N_ * M_;

    auto cvtOn = [&](cudaStream_t s, const float* src, __half* dst, long long n) {
        int n8 = (int)(n / 8);
        cvt_f32_f16<<<(n8 + 255) / 256, 256, 0, s>>>(
            (const float4*)src, (uint2*)dst, n8);
    };

    // ---- fork ----
    cudaEventRecord(eFork, 0);
    cudaStreamWaitEvent(sB, eFork, 0);
    cudaStreamWaitEvent(sC, eFork, 0);

    // sC: cvt Wk (critical for GEMM1), then cvt k, cvt Wf
    cvtOn(sC, Wk, Wkh, (long long)H_ * O_ * D_);
    cudaEventRecord(eWk, sC);
    cvtOn(sC, k_in, kh, (long long)N_ * O_);
    cudaEventRecord(eK, sC);
    cvtOn(sC, Wf, Wfh, (long long)O_ * H_ * O_);
    cudaEventRecord(eWf, sC);

    // spine: cvt mems only
    cvtOn(0, mems, memsh, (long long)H_ * M_ * D_);
    cudaEventRecord(eMems, 0);

    // sB: cvt Wv -> GEMM2 -> GEMM3b
    cvtOn(sB, Wv, Wvh, (long long)H_ * O_ * D_);
    cudaStreamWaitEvent(sB, eMems, 0);
    {
        dim3 grid(O_ / TBN, M_ / TBM, H_);
        gemm_nt_f16<<<grid, 256, SMEM_DYN, sB>>>(memsh, MD, D_, Wvh, OD, D_,
                                                 memvalh, MO, O_, bv, O_, D_, 0, 1,
                                                 nullptr,
                                                 nullptr, 0, 0, 0, 0,
                                                 nullptr, 0, 0, 0,
                                                 0, 0, 0.f);
    }
    cudaStreamWaitEvent(sB, eWf, 0);
    {
        dim3 grid(M_ / TBN, O_ / TBM, H_);
        gemm_nt_f16<<<grid, 256, SMEM_DYN, sB>>>(Wfh, O_, (long long)H_ * O_,
                                                 memvalh, MO, O_,
                                                 GTh, MO, M_, nullptr, 0, O_, 0, 1,
                                                 nullptr,
                                                 nullptr, 0, 0, 0, 0,
                                                 nullptr, 0, 0, 0,
                                                 0, 0, 0.f);
    }
    cudaEventRecord(e3b, sB);

    // spine: GEMM1 exp mode (exp(logit + bk), row partial sums)
    cudaStreamWaitEvent(0, eWk, 0);
    {
        dim3 grid(O_ / TBN, M_ / TBM, H_);
        gemm_nt_f16<<<grid, 256, SMEM_DYN>>>(memsh, MD, D_, Wkh, OD, D_,
                                             memkeyh, MO, O_, bk, O_, D_, 0, 2,
                                             partialS3,
                                             nullptr, 0, 0, 0, 0,
                                             nullptr, 0, 0, 0,
                                             0, 0, 0.0f);
    }

    // spine: GEMM4 exp mode, col-scale fused from partialS3 (invS3 recompute)
    cudaStreamWaitEvent(0, eK, 0);
    {
        dim3 grid(M_ / TBN, N_ / TBM, H_);
        gemm_nt_f16<<<grid, 256, SMEM_DYN>>>(kh, 0, O_, memkeyh, MO, O_,
                                             atth, NM, M_, nullptr, 0, O_, 0, 2,
                                             partialS,
                                             nullptr, 0, 0, 0, 0,
                                             partialS3, M_, MT3, ROWS3,
                                             0, 0, 4.0f);
    }

    // join: GEMM6 split-K=4 by head group, row-scale fused, fp16 partials
    cudaStreamWaitEvent(0, e3b, 0);
    {
        dim3 grid(O_ / TBN, N_ / TBM, SPLIT6);
        gemm_nt_f16<<<grid, 256, SMEM_DYN>>>(atth, NM, M_, GTh, MO, M_,
                                             part6, (long long)NO_, O_,
                                             nullptr, 0,
                                             HPS * M_, M_, 1,
                                             nullptr,
                                             partialS, HPS, N_, MTILES, ROWS_TOT,
                                             nullptr, 0, 0, 0,
                                             (long long)HPS * NM, (long long)HPS * MO,
                                             0.f);
    }
    {
        int n4 = (int)(NO_ / 4);
        reduce_out<<<(n4 + 255) / 256, 256>>>((const uint2*)part6, bf,
                                              (float4*)out, n4);
    }
}